// round 1
// baseline (speedup 1.0000x reference)
#include <cuda_runtime.h>
#include <cstdint>
#include <cstdio>

#define B_DIM 2
#define T_DIM 4096
#define C_DIM 1024
#define H_DIM 16
#define D_DIM 64

// Scratch (static device allocations - allowed)
__device__ float g_qkv[(size_t)B_DIM * T_DIM * 3 * C_DIM];  // [B,T,3,H,D] = 25.2M floats
__device__ float g_att[(size_t)B_DIM * T_DIM * C_DIM];      // [B,T,C]

// ---------------------------------------------------------------------------
// C[M,N] = A[M,K] @ B[N,K]^T   (both row-major, K contiguous)
// 128x128 tile, BK=16, 256 threads, 8x8 microtile per thread
// ---------------------------------------------------------------------------
__global__ __launch_bounds__(256) void sgemm_nt(
    const float* __restrict__ A, const float* __restrict__ Bm,
    float* __restrict__ Cm, int M, int N, int K)
{
    __shared__ float As[16][128 + 4];
    __shared__ float Bs[16][128 + 4];

    const int tid = threadIdx.x;
    const int tx = tid & 15;
    const int ty = tid >> 4;
    const int bm = blockIdx.y;
    const int bn = blockIdx.x;

    const float* Ab = A + (size_t)bm * 128 * K;
    const float* Bb = Bm + (size_t)bn * 128 * K;

    float acc[8][8];
#pragma unroll
    for (int i = 0; i < 8; i++)
#pragma unroll
        for (int j = 0; j < 8; j++) acc[i][j] = 0.0f;

    for (int kt = 0; kt < K; kt += 16) {
#pragma unroll
        for (int i = 0; i < 2; i++) {
            int f = tid + i * 256;          // 0..511
            int r = f >> 2;
            int c4 = (f & 3) << 2;
            float4 va = *(const float4*)(Ab + (size_t)r * K + kt + c4);
            As[c4 + 0][r] = va.x; As[c4 + 1][r] = va.y;
            As[c4 + 2][r] = va.z; As[c4 + 3][r] = va.w;
            float4 vb = *(const float4*)(Bb + (size_t)r * K + kt + c4);
            Bs[c4 + 0][r] = vb.x; Bs[c4 + 1][r] = vb.y;
            Bs[c4 + 2][r] = vb.z; Bs[c4 + 3][r] = vb.w;
        }
        __syncthreads();

#pragma unroll
        for (int k = 0; k < 16; k++) {
            float4 a0 = *(const float4*)&As[k][ty * 8];
            float4 a1 = *(const float4*)&As[k][ty * 8 + 4];
            float4 b0 = *(const float4*)&Bs[k][tx * 8];
            float4 b1 = *(const float4*)&Bs[k][tx * 8 + 4];
            float a[8] = {a0.x, a0.y, a0.z, a0.w, a1.x, a1.y, a1.z, a1.w};
            float b[8] = {b0.x, b0.y, b0.z, b0.w, b1.x, b1.y, b1.z, b1.w};
#pragma unroll
            for (int i = 0; i < 8; i++)
#pragma unroll
                for (int j = 0; j < 8; j++) acc[i][j] += a[i] * b[j];
        }
        __syncthreads();
    }

#pragma unroll
    for (int i = 0; i < 8; i++) {
        size_t row = (size_t)bm * 128 + ty * 8 + i;
        float* cp = Cm + row * N + bn * 128 + tx * 8;
        float4 o0 = make_float4(acc[i][0], acc[i][1], acc[i][2], acc[i][3]);
        float4 o1 = make_float4(acc[i][4], acc[i][5], acc[i][6], acc[i][7]);
        *(float4*)(cp) = o0;
        *(float4*)(cp + 4) = o1;
    }
}

// ---------------------------------------------------------------------------
// Flash attention, fp32, causal. One CTA per (q-tile of 64, head, batch).
// 256 threads: tx=tid&15, ty=tid>>4.
// S rows: ty+16i, S cols: tx+16j  (conflict-free float4 over d)
// O rows: ty+16i, O cols: 4tx+j   (conflict-free float4 V loads, coalesced store)
// ---------------------------------------------------------------------------
#define ALD 68  // padded leading dim (16B-aligned)

__global__ __launch_bounds__(256) void attn_kernel(
    const float* __restrict__ qkv, float* __restrict__ out)
{
    extern __shared__ float sm[];
    float* Qs = sm;                 // [64][68]
    float* Ks = Qs + 64 * ALD;
    float* Vs = Ks + 64 * ALD;
    float* Ps = Vs + 64 * ALD;
    float* Ms = Ps + 64 * ALD;      // [64] running max
    float* Ls = Ms + 64;            // [64] running sum
    float* Al = Ls + 64;            // [64] alpha

    const int qt = blockIdx.x;
    const int h  = blockIdx.y;
    const int b  = blockIdx.z;
    const int tid = threadIdx.x;
    const int tx = tid & 15;
    const int ty = tid >> 4;
    const int q0 = qt * 64;

    const float* qptr = qkv + (size_t)b * T_DIM * 3072 + h * 64;  // + t*3072 + d
    const float* kptr = qptr + 1024;
    const float* vptr = qptr + 2048;

    // load Q tile (64 rows x 64 floats)
#pragma unroll
    for (int i = 0; i < 4; i++) {
        int f = tid + i * 256;          // 0..1023
        int r = f >> 4;
        int c = (f & 15) << 2;
        *(float4*)(Qs + r * ALD + c) =
            *(const float4*)(qptr + (size_t)(q0 + r) * 3072 + c);
    }
    if (tid < 64) { Ms[tid] = -1e30f; Ls[tid] = 0.0f; }

    float acc[4][4];
#pragma unroll
    for (int i = 0; i < 4; i++)
#pragma unroll
        for (int j = 0; j < 4; j++) acc[i][j] = 0.0f;

    const float scale = 0.125f;  // 1/sqrt(64)

    for (int kt = 0; kt <= qt; kt++) {
        const int k0 = kt * 64;
        __syncthreads();  // previous iteration done with Ks/Vs/Ps
#pragma unroll
        for (int i = 0; i < 4; i++) {
            int f = tid + i * 256;
            int r = f >> 4;
            int c = (f & 15) << 2;
            *(float4*)(Ks + r * ALD + c) =
                *(const float4*)(kptr + (size_t)(k0 + r) * 3072 + c);
            *(float4*)(Vs + r * ALD + c) =
                *(const float4*)(vptr + (size_t)(k0 + r) * 3072 + c);
        }
        __syncthreads();

        // S = Q @ K^T
        float s[4][4];
#pragma unroll
        for (int i = 0; i < 4; i++)
#pragma unroll
            for (int j = 0; j < 4; j++) s[i][j] = 0.0f;

#pragma unroll
        for (int d = 0; d < 64; d += 4) {
            float4 qv[4], kv[4];
#pragma unroll
            for (int i = 0; i < 4; i++)
                qv[i] = *(const float4*)(Qs + (ty + 16 * i) * ALD + d);
#pragma unroll
            for (int j = 0; j < 4; j++)
                kv[j] = *(const float4*)(Ks + (tx + 16 * j) * ALD + d);
#pragma unroll
            for (int i = 0; i < 4; i++)
#pragma unroll
                for (int j = 0; j < 4; j++)
                    s[i][j] += qv[i].x * kv[j].x + qv[i].y * kv[j].y +
                               qv[i].z * kv[j].z + qv[i].w * kv[j].w;
        }

        // scale + causal mask, store to Ps
        const bool diag = (kt == qt);
#pragma unroll
        for (int i = 0; i < 4; i++) {
            int r = ty + 16 * i;
#pragma unroll
            for (int j = 0; j < 4; j++) {
                int c = tx + 16 * j;
                float v = s[i][j] * scale;
                if (diag && c > r) v = -1e30f;
                Ps[r * ALD + c] = v;
            }
        }
        __syncthreads();

        // online softmax: 4 threads per row (same warp, lanes g=tid&3)
        {
            int r = tid >> 2;
            int g = tid & 3;
            float* prow = Ps + r * ALD + g * 16;
            float v[16];
            *(float4*)&v[0]  = *(const float4*)(prow);
            *(float4*)&v[4]  = *(const float4*)(prow + 4);
            *(float4*)&v[8]  = *(const float4*)(prow + 8);
            *(float4*)&v[12] = *(const float4*)(prow + 12);

            float mx = v[0];
#pragma unroll
            for (int c = 1; c < 16; c++) mx = fmaxf(mx, v[c]);
            mx = fmaxf(mx, __shfl_xor_sync(0xffffffffu, mx, 1));
            mx = fmaxf(mx, __shfl_xor_sync(0xffffffffu, mx, 2));

            float mold = Ms[r];
            float mnew = fmaxf(mold, mx);

            float sum = 0.0f;
#pragma unroll
            for (int c = 0; c < 16; c++) {
                v[c] = __expf(v[c] - mnew);
                sum += v[c];
            }
            sum += __shfl_xor_sync(0xffffffffu, sum, 1);
            sum += __shfl_xor_sync(0xffffffffu, sum, 2);

            *(float4*)(prow)      = *(float4*)&v[0];
            *(float4*)(prow + 4)  = *(float4*)&v[4];
            *(float4*)(prow + 8)  = *(float4*)&v[8];
            *(float4*)(prow + 12) = *(float4*)&v[12];

            if (g == 0) {
                float alpha = __expf(mold - mnew);
                Al[r] = alpha;
                Ls[r] = Ls[r] * alpha + sum;
                Ms[r] = mnew;
            }
        }
        __syncthreads();

        // rescale O, then O += P @ V
#pragma unroll
        for (int i = 0; i < 4; i++) {
            float a = Al[ty + 16 * i];
#pragma unroll
            for (int j = 0; j < 4; j++) acc[i][j] *= a;
        }

#pragma unroll
        for (int c = 0; c < 64; c += 4) {
            float p4[4][4];
#pragma unroll
            for (int i = 0; i < 4; i++)
                *(float4*)&p4[i][0] = *(const float4*)(Ps + (ty + 16 * i) * ALD + c);
#pragma unroll
            for (int cc = 0; cc < 4; cc++) {
                float vrow[4];
                *(float4*)vrow = *(const float4*)(Vs + (c + cc) * ALD + 4 * tx);
#pragma unroll
                for (int i = 0; i < 4; i++)
#pragma unroll
                    for (int j = 0; j < 4; j++)
                        acc[i][j] += p4[i][cc] * vrow[j];
            }
        }
    }
    __syncthreads();

    // normalize and write out: att[b, q0+r, h*64 + (4tx+j)]
    float* obase = out + (size_t)b * T_DIM * C_DIM + h * 64;
#pragma unroll
    for (int i = 0; i < 4; i++) {
        int r = ty + 16 * i;
        float inv = 1.0f / Ls[r];
        float4 o = make_float4(acc[i][0] * inv, acc[i][1] * inv,
                               acc[i][2] * inv, acc[i][3] * inv);
        *(float4*)(obase + (size_t)(q0 + r) * C_DIM + 4 * tx) = o;
    }
}

// ---------------------------------------------------------------------------
// launch
// ---------------------------------------------------------------------------
extern "C" void kernel_launch(void* const* d_in, const int* in_sizes, int n_in,
                              void* d_out, int out_size)
{
    const float* x     = (const float*)d_in[0];   // [B,T,C]
    const float* wqkv  = (const float*)d_in[1];   // [3C,C]
    const float* wout  = (const float*)d_in[2];   // [C,C]
    float* out = (float*)d_out;                   // [B,T,C]

    float* qkv = nullptr;
    float* att = nullptr;
    cudaGetSymbolAddress((void**)&qkv, g_qkv);
    cudaGetSymbolAddress((void**)&att, g_att);

    const int M = B_DIM * T_DIM;   // 8192

    // 1) QKV projection: [M, 3C] = x[M,C] @ W_qkv[3C,C]^T
    sgemm_nt<<<dim3(3 * C_DIM / 128, M / 128), 256>>>(x, wqkv, qkv, M, 3 * C_DIM, C_DIM);

    // 2) causal flash attention
    const int smem_bytes = (4 * 64 * ALD + 3 * 64) * sizeof(float);  // 70400
    cudaFuncSetAttribute(attn_kernel, cudaFuncAttributeMaxDynamicSharedMemorySize,
                         smem_bytes);
    attn_kernel<<<dim3(T_DIM / 64, H_DIM, B_DIM), 256, smem_bytes>>>(qkv, att);

    // 3) output projection: [M, C] = att[M,C] @ W_out[C,C]^T
    sgemm_nt<<<dim3(C_DIM / 128, M / 128), 256>>>(att, wout, out, M, C_DIM, C_DIM);
}

// round 3
// speedup vs baseline: 1.2538x; 1.2538x over previous
#include <cuda_runtime.h>
#include <cuda_bf16.h>
#include <cstdint>

#define B_DIM 2
#define T_DIM 4096
#define C_DIM 1024
#define H_DIM 16
#define D_DIM 64
#define MROWS (B_DIM * T_DIM)   // 8192
#define KDIM  C_DIM             // 1024

// ---------------- static device scratch (no allocs allowed) ----------------
__device__ float g_qkv[(size_t)MROWS * 3 * C_DIM];   // [B,T,3,H,D]
__device__ float g_att[(size_t)MROWS * C_DIM];       // [B,T,C]

__device__ __align__(256) __nv_bfloat16 g_xh[(size_t)MROWS * KDIM];
__device__ __align__(256) __nv_bfloat16 g_xl[(size_t)MROWS * KDIM];
__device__ __align__(256) __nv_bfloat16 g_wqh[(size_t)3 * C_DIM * KDIM];
__device__ __align__(256) __nv_bfloat16 g_wql[(size_t)3 * C_DIM * KDIM];
__device__ __align__(256) __nv_bfloat16 g_woh[(size_t)C_DIM * KDIM];
__device__ __align__(256) __nv_bfloat16 g_wol[(size_t)C_DIM * KDIM];
__device__ __align__(256) __nv_bfloat16 g_ah[(size_t)MROWS * KDIM];
__device__ __align__(256) __nv_bfloat16 g_al[(size_t)MROWS * KDIM];

// ---------------------------------------------------------------------------
// split fp32 -> bf16 hi + bf16 lo  (lo = bf16(x - float(hi)))
// ---------------------------------------------------------------------------
__global__ __launch_bounds__(256) void split_bf16(
    const float4* __restrict__ in, __nv_bfloat162* __restrict__ hi,
    __nv_bfloat162* __restrict__ lo, int n4)
{
    int i = blockIdx.x * blockDim.x + threadIdx.x;
    if (i >= n4) return;
    float4 v = in[i];
    __nv_bfloat16 h0 = __float2bfloat16(v.x);
    __nv_bfloat16 h1 = __float2bfloat16(v.y);
    __nv_bfloat16 h2 = __float2bfloat16(v.z);
    __nv_bfloat16 h3 = __float2bfloat16(v.w);
    __nv_bfloat16 l0 = __float2bfloat16(v.x - __bfloat162float(h0));
    __nv_bfloat16 l1 = __float2bfloat16(v.y - __bfloat162float(h1));
    __nv_bfloat16 l2 = __float2bfloat16(v.z - __bfloat162float(h2));
    __nv_bfloat16 l3 = __float2bfloat16(v.w - __bfloat162float(h3));
    hi[2 * i]     = __nv_bfloat162(h0, h1);
    hi[2 * i + 1] = __nv_bfloat162(h2, h3);
    lo[2 * i]     = __nv_bfloat162(l0, l1);
    lo[2 * i + 1] = __nv_bfloat162(l2, l3);
}

// ---------------------------------------------------------------------------
// PTX helpers (plain PTX only — no 'a'-suffix features reach ptxas here)
// ---------------------------------------------------------------------------
__device__ __forceinline__ uint32_t cvta_s(const void* p) {
    uint32_t a;
    asm("{ .reg .u64 t; cvta.to.shared.u64 t, %1; cvt.u32.u64 %0, t; }"
        : "=r"(a) : "l"(p));
    return a;
}

__device__ __forceinline__ void cp16(uint32_t dst, const void* src) {
    asm volatile("cp.async.cg.shared.global [%0], [%1], 16;"
                 :: "r"(dst), "l"(src) : "memory");
}

__device__ __forceinline__ void ldm4(uint32_t addr, uint32_t& r0, uint32_t& r1,
                                     uint32_t& r2, uint32_t& r3) {
    asm volatile("ldmatrix.sync.aligned.m8n8.x4.shared.b16 {%0,%1,%2,%3}, [%4];"
                 : "=r"(r0), "=r"(r1), "=r"(r2), "=r"(r3) : "r"(addr));
}

__device__ __forceinline__ void mma_bf16(float* d, const uint32_t* a,
                                         uint32_t b0, uint32_t b1) {
    asm volatile(
        "mma.sync.aligned.m16n8k16.row.col.f32.bf16.bf16.f32 "
        "{%0,%1,%2,%3}, {%4,%5,%6,%7}, {%8,%9}, {%0,%1,%2,%3};"
        : "+f"(d[0]), "+f"(d[1]), "+f"(d[2]), "+f"(d[3])
        : "r"(a[0]), "r"(a[1]), "r"(a[2]), "r"(a[3]), "r"(b0), "r"(b1));
}

// ---------------------------------------------------------------------------
// C[M,N](fp32) = (Ah+Al)[M,K] @ (Bh+Bl)[N,K]^T  via 3-term split-bf16 mma.sync
// CTA 128x128, BK=32, 3-stage cp.async, 256 threads (8 warps, 2x4, 64x32 each)
// smem tiles: 128 rows x pitch 40 bf16 (80B) -> conflict-free ldmatrix
// ---------------------------------------------------------------------------
#define PITCH   40                       // bf16 elems per smem row (80 B)
#define TILEB   (128 * PITCH * 2)        // 10240 B per 128x32 tile
#define STAGEB  (4 * TILEB)              // Ah,Al,Bh,Bl = 40960 B
#define NSTAGE  3

// load one 128x32 bf16 tile into smem (80B pitch), 512 x 16B chunks
__device__ __forceinline__ void ld_tile(const __nv_bfloat16* __restrict__ G,
                                        int K, int row0, int k0,
                                        uint32_t dstbase, int tid)
{
#pragma unroll
    for (int t = 0; t < 2; t++) {
        int idx = tid + t * 256;          // 0..511
        int r = idx >> 2;
        int c = idx & 3;
        cp16(dstbase + r * 80 + c * 16,
             G + (size_t)(row0 + r) * K + k0 + c * 8);
    }
}

__global__ __launch_bounds__(256) void gemm_bf16x3(
    const __nv_bfloat16* __restrict__ Ah, const __nv_bfloat16* __restrict__ Al,
    const __nv_bfloat16* __restrict__ Bh, const __nv_bfloat16* __restrict__ Bl,
    float* __restrict__ C, int N, int K)
{
    extern __shared__ __align__(128) char smraw[];
    const uint32_t smbase = cvta_s(smraw);

    const int tid  = threadIdx.x;
    const int wid  = tid >> 5;
    const int lane = tid & 31;
    const int n0 = blockIdx.x * 128;
    const int m0 = blockIdx.y * 128;
    const int wm = (wid & 1) * 64;        // warp M offset in CTA tile
    const int wn = (wid >> 1) * 32;       // warp N offset

    const int lr = lane & 15;             // ldmatrix row-within-tile
    const int lc = lane >> 4;             // ldmatrix 16B-chunk select

    float acc[4][4][4];
#pragma unroll
    for (int i = 0; i < 4; i++)
#pragma unroll
        for (int j = 0; j < 4; j++)
#pragma unroll
            for (int k = 0; k < 4; k++) acc[i][j][k] = 0.0f;

    const int nch = K / 32;               // 32 chunks

    // prologue: stage chunks 0..2
#pragma unroll
    for (int c = 0; c < NSTAGE; c++) {
        uint32_t sb = smbase + c * STAGEB;
        ld_tile(Ah, K, m0, c * 32, sb, tid);
        ld_tile(Al, K, m0, c * 32, sb + TILEB, tid);
        ld_tile(Bh, K, n0, c * 32, sb + 2 * TILEB, tid);
        ld_tile(Bl, K, n0, c * 32, sb + 3 * TILEB, tid);
        asm volatile("cp.async.commit_group;" ::: "memory");
    }

    for (int c = 0; c < nch; c++) {
        asm volatile("cp.async.wait_group %0;" :: "n"(NSTAGE - 1) : "memory");
        __syncthreads();

        uint32_t sb  = smbase + (c % NSTAGE) * STAGEB;
        uint32_t aHb = sb + (wm + lr) * 80;
        uint32_t aLb = aHb + TILEB;
        uint32_t bHb = sb + 2 * TILEB + (wn + lr) * 80;
        uint32_t bLb = bHb + TILEB;

#pragma unroll
        for (int ks = 0; ks < 2; ks++) {
            uint32_t koff = (ks * 2 + lc) * 16;
            uint32_t ah[4][4], al4[4][4];
#pragma unroll
            for (int mt = 0; mt < 4; mt++) {
                ldm4(aHb + mt * 16 * 80 + koff,
                     ah[mt][0], ah[mt][1], ah[mt][2], ah[mt][3]);
                ldm4(aLb + mt * 16 * 80 + koff,
                     al4[mt][0], al4[mt][1], al4[mt][2], al4[mt][3]);
            }
            uint32_t bh[2][4], bl[2][4];
#pragma unroll
            for (int p = 0; p < 2; p++) {
                ldm4(bHb + p * 16 * 80 + koff,
                     bh[p][0], bh[p][1], bh[p][2], bh[p][3]);
                ldm4(bLb + p * 16 * 80 + koff,
                     bl[p][0], bl[p][1], bl[p][2], bl[p][3]);
            }
#pragma unroll
            for (int mt = 0; mt < 4; mt++) {
#pragma unroll
                for (int nt = 0; nt < 4; nt++) {
                    const int p = nt >> 1, h = nt & 1;
                    mma_bf16(acc[mt][nt], ah[mt],  bh[p][h], bh[p][2 + h]);
                    mma_bf16(acc[mt][nt], al4[mt], bh[p][h], bh[p][2 + h]);
                    mma_bf16(acc[mt][nt], ah[mt],  bl[p][h], bl[p][2 + h]);
                }
            }
        }
        __syncthreads();

        if (c + NSTAGE < nch) {
            uint32_t db = smbase + (c % NSTAGE) * STAGEB;
            int kk = (c + NSTAGE) * 32;
            ld_tile(Ah, K, m0, kk, db, tid);
            ld_tile(Al, K, m0, kk, db + TILEB, tid);
            ld_tile(Bh, K, n0, kk, db + 2 * TILEB, tid);
            ld_tile(Bl, K, n0, kk, db + 3 * TILEB, tid);
        }
        asm volatile("cp.async.commit_group;" ::: "memory");
    }

    // epilogue: per mma frag, thread holds (m=lane/4, n=2*(lane%4)) and (m+8, same n)
    const int er = lane >> 2;
    const int ec = (lane & 3) * 2;
#pragma unroll
    for (int mt = 0; mt < 4; mt++) {
#pragma unroll
        for (int nt = 0; nt < 4; nt++) {
            size_t row = (size_t)(m0 + wm + mt * 16 + er);
            int col = n0 + wn + nt * 8 + ec;
            *(float2*)(C + row * N + col) =
                make_float2(acc[mt][nt][0], acc[mt][nt][1]);
            *(float2*)(C + (row + 8) * N + col) =
                make_float2(acc[mt][nt][2], acc[mt][nt][3]);
        }
    }
}

// ---------------------------------------------------------------------------
// Flash attention, fp32, causal (unchanged — next round's target)
// ---------------------------------------------------------------------------
#define ALD 68

__global__ __launch_bounds__(256) void attn_kernel(
    const float* __restrict__ qkv, float* __restrict__ out)
{
    extern __shared__ float sm[];
    float* Qs = sm;
    float* Ks = Qs + 64 * ALD;
    float* Vs = Ks + 64 * ALD;
    float* Ps = Vs + 64 * ALD;
    float* Ms = Ps + 64 * ALD;
    float* Ls = Ms + 64;
    float* Al = Ls + 64;

    const int qt = blockIdx.x;
    const int h  = blockIdx.y;
    const int b  = blockIdx.z;
    const int tid = threadIdx.x;
    const int tx = tid & 15;
    const int ty = tid >> 4;
    const int q0 = qt * 64;

    const float* qptr = qkv + (size_t)b * T_DIM * 3072 + h * 64;
    const float* kptr = qptr + 1024;
    const float* vptr = qptr + 2048;

#pragma unroll
    for (int i = 0; i < 4; i++) {
        int f = tid + i * 256;
        int r = f >> 4;
        int c = (f & 15) << 2;
        *(float4*)(Qs + r * ALD + c) =
            *(const float4*)(qptr + (size_t)(q0 + r) * 3072 + c);
    }
    if (tid < 64) { Ms[tid] = -1e30f; Ls[tid] = 0.0f; }

    float acc[4][4];
#pragma unroll
    for (int i = 0; i < 4; i++)
#pragma unroll
        for (int j = 0; j < 4; j++) acc[i][j] = 0.0f;

    const float scale = 0.125f;

    for (int kt = 0; kt <= qt; kt++) {
        const int k0 = kt * 64;
        __syncthreads();
#pragma unroll
        for (int i = 0; i < 4; i++) {
            int f = tid + i * 256;
            int r = f >> 4;
            int c = (f & 15) << 2;
            *(float4*)(Ks + r * ALD + c) =
                *(const float4*)(kptr + (size_t)(k0 + r) * 3072 + c);
            *(float4*)(Vs + r * ALD + c) =
                *(const float4*)(vptr + (size_t)(k0 + r) * 3072 + c);
        }
        __syncthreads();

        float s[4][4];
#pragma unroll
        for (int i = 0; i < 4; i++)
#pragma unroll
            for (int j = 0; j < 4; j++) s[i][j] = 0.0f;

#pragma unroll
        for (int d = 0; d < 64; d += 4) {
            float4 qv[4], kv[4];
#pragma unroll
            for (int i = 0; i < 4; i++)
                qv[i] = *(const float4*)(Qs + (ty + 16 * i) * ALD + d);
#pragma unroll
            for (int j = 0; j < 4; j++)
                kv[j] = *(const float4*)(Ks + (tx + 16 * j) * ALD + d);
#pragma unroll
            for (int i = 0; i < 4; i++)
#pragma unroll
                for (int j = 0; j < 4; j++)
                    s[i][j] += qv[i].x * kv[j].x + qv[i].y * kv[j].y +
                               qv[i].z * kv[j].z + qv[i].w * kv[j].w;
        }

        const bool diag = (kt == qt);
#pragma unroll
        for (int i = 0; i < 4; i++) {
            int r = ty + 16 * i;
#pragma unroll
            for (int j = 0; j < 4; j++) {
                int c = tx + 16 * j;
                float v = s[i][j] * scale;
                if (diag && c > r) v = -1e30f;
                Ps[r * ALD + c] = v;
            }
        }
        __syncthreads();

        {
            int r = tid >> 2;
            int g = tid & 3;
            float* prow = Ps + r * ALD + g * 16;
            float v[16];
            *(float4*)&v[0]  = *(const float4*)(prow);
            *(float4*)&v[4]  = *(const float4*)(prow + 4);
            *(float4*)&v[8]  = *(const float4*)(prow + 8);
            *(float4*)&v[12] = *(const float4*)(prow + 12);

            float mx = v[0];
#pragma unroll
            for (int c = 1; c < 16; c++) mx = fmaxf(mx, v[c]);
            mx = fmaxf(mx, __shfl_xor_sync(0xffffffffu, mx, 1));
            mx = fmaxf(mx, __shfl_xor_sync(0xffffffffu, mx, 2));

            float mold = Ms[r];
            float mnew = fmaxf(mold, mx);

            float sum = 0.0f;
#pragma unroll
            for (int c = 0; c < 16; c++) {
                v[c] = __expf(v[c] - mnew);
                sum += v[c];
            }
            sum += __shfl_xor_sync(0xffffffffu, sum, 1);
            sum += __shfl_xor_sync(0xffffffffu, sum, 2);

            *(float4*)(prow)      = *(float4*)&v[0];
            *(float4*)(prow + 4)  = *(float4*)&v[4];
            *(float4*)(prow + 8)  = *(float4*)&v[8];
            *(float4*)(prow + 12) = *(float4*)&v[12];

            if (g == 0) {
                float alpha = __expf(mold - mnew);
                Al[r] = alpha;
                Ls[r] = Ls[r] * alpha + sum;
                Ms[r] = mnew;
            }
        }
        __syncthreads();

#pragma unroll
        for (int i = 0; i < 4; i++) {
            float a = Al[ty + 16 * i];
#pragma unroll
            for (int j = 0; j < 4; j++) acc[i][j] *= a;
        }

#pragma unroll
        for (int c = 0; c < 64; c += 4) {
            float p4[4][4];
#pragma unroll
            for (int i = 0; i < 4; i++)
                *(float4*)&p4[i][0] = *(const float4*)(Ps + (ty + 16 * i) * ALD + c);
#pragma unroll
            for (int cc = 0; cc < 4; cc++) {
                float vrow[4];
                *(float4*)vrow = *(const float4*)(Vs + (c + cc) * ALD + 4 * tx);
#pragma unroll
                for (int i = 0; i < 4; i++)
#pragma unroll
                    for (int j = 0; j < 4; j++)
                        acc[i][j] += p4[i][cc] * vrow[j];
            }
        }
    }
    __syncthreads();

    float* obase = out + (size_t)b * T_DIM * C_DIM + h * 64;
#pragma unroll
    for (int i = 0; i < 4; i++) {
        int r = ty + 16 * i;
        float inv = 1.0f / Ls[r];
        float4 o = make_float4(acc[i][0] * inv, acc[i][1] * inv,
                               acc[i][2] * inv, acc[i][3] * inv);
        *(float4*)(obase + (size_t)(q0 + r) * C_DIM + 4 * tx) = o;
    }
}

// ---------------------------------------------------------------------------
// launch
// ---------------------------------------------------------------------------
extern "C" void kernel_launch(void* const* d_in, const int* in_sizes, int n_in,
                              void* d_out, int out_size)
{
    const float* x    = (const float*)d_in[0];
    const float* wqkv = (const float*)d_in[1];
    const float* wout = (const float*)d_in[2];
    float* out = (float*)d_out;

    float *qkv, *att;
    __nv_bfloat16 *xh, *xl, *wqh, *wql, *woh, *wol, *ah, *al;
    cudaGetSymbolAddress((void**)&qkv, g_qkv);
    cudaGetSymbolAddress((void**)&att, g_att);
    cudaGetSymbolAddress((void**)&xh, g_xh);
    cudaGetSymbolAddress((void**)&xl, g_xl);
    cudaGetSymbolAddress((void**)&wqh, g_wqh);
    cudaGetSymbolAddress((void**)&wql, g_wql);
    cudaGetSymbolAddress((void**)&woh, g_woh);
    cudaGetSymbolAddress((void**)&wol, g_wol);
    cudaGetSymbolAddress((void**)&ah, g_ah);
    cudaGetSymbolAddress((void**)&al, g_al);

    const int gemm_smem = NSTAGE * STAGEB;  // 122880
    cudaFuncSetAttribute(gemm_bf16x3, cudaFuncAttributeMaxDynamicSharedMemorySize,
                         gemm_smem);

    // split inputs to bf16 hi/lo
    {
        int n4 = MROWS * KDIM / 4;
        split_bf16<<<(n4 + 255) / 256, 256>>>((const float4*)x,
            (__nv_bfloat162*)xh, (__nv_bfloat162*)xl, n4);
        n4 = 3 * C_DIM * KDIM / 4;
        split_bf16<<<(n4 + 255) / 256, 256>>>((const float4*)wqkv,
            (__nv_bfloat162*)wqh, (__nv_bfloat162*)wql, n4);
        n4 = C_DIM * KDIM / 4;
        split_bf16<<<(n4 + 255) / 256, 256>>>((const float4*)wout,
            (__nv_bfloat162*)woh, (__nv_bfloat162*)wol, n4);
    }

    // 1) QKV projection: [8192, 3072]
    gemm_bf16x3<<<dim3(3 * C_DIM / 128, MROWS / 128), 256, gemm_smem>>>(
        xh, xl, wqh, wql, qkv, 3 * C_DIM, KDIM);

    // 2) causal flash attention (fp32)
    const int attn_smem = (4 * 64 * ALD + 3 * 64) * sizeof(float);
    cudaFuncSetAttribute(attn_kernel, cudaFuncAttributeMaxDynamicSharedMemorySize,
                         attn_smem);
    attn_kernel<<<dim3(T_DIM / 64, H_DIM, B_DIM), 256, attn_smem>>>(qkv, att);

    // split attention output
    {
        int n4 = MROWS * KDIM / 4;
        split_bf16<<<(n4 + 255) / 256, 256>>>((const float4*)att,
            (__nv_bfloat162*)ah, (__nv_bfloat162*)al, n4);
    }

    // 3) output projection: [8192, 1024]
    gemm_bf16x3<<<dim3(C_DIM / 128, MROWS / 128), 256, gemm_smem>>>(
        ah, al, woh, wol, out, C_DIM, KDIM);
}

// round 4
// speedup vs baseline: 2.4391x; 1.9453x over previous
#include <cuda_runtime.h>
#include <cuda_bf16.h>
#include <cstdint>

#define B_DIM 2
#define T_DIM 4096
#define C_DIM 1024
#define H_DIM 16
#define D_DIM 64
#define MROWS (B_DIM * T_DIM)   // 8192
#define KDIM  C_DIM             // 1024

// ---------------- static device scratch (no allocs allowed) ----------------
__device__ float g_qkv[(size_t)MROWS * 3 * C_DIM];   // [B,T,3,H,D]

__device__ __align__(256) __nv_bfloat16 g_xh[(size_t)MROWS * KDIM];
__device__ __align__(256) __nv_bfloat16 g_xl[(size_t)MROWS * KDIM];
__device__ __align__(256) __nv_bfloat16 g_wqh[(size_t)3 * C_DIM * KDIM];
__device__ __align__(256) __nv_bfloat16 g_wql[(size_t)3 * C_DIM * KDIM];
__device__ __align__(256) __nv_bfloat16 g_woh[(size_t)C_DIM * KDIM];
__device__ __align__(256) __nv_bfloat16 g_wol[(size_t)C_DIM * KDIM];
__device__ __align__(256) __nv_bfloat16 g_ah[(size_t)MROWS * KDIM];
__device__ __align__(256) __nv_bfloat16 g_al[(size_t)MROWS * KDIM];

// per-head [b,h,t,d] bf16 hi/lo for attention
__device__ __align__(256) __nv_bfloat16 g_qh2[(size_t)MROWS * C_DIM];
__device__ __align__(256) __nv_bfloat16 g_ql2[(size_t)MROWS * C_DIM];
__device__ __align__(256) __nv_bfloat16 g_kh2[(size_t)MROWS * C_DIM];
__device__ __align__(256) __nv_bfloat16 g_kl2[(size_t)MROWS * C_DIM];
__device__ __align__(256) __nv_bfloat16 g_vh2[(size_t)MROWS * C_DIM];
__device__ __align__(256) __nv_bfloat16 g_vl2[(size_t)MROWS * C_DIM];

// ---------------------------------------------------------------------------
// PTX helpers (plain PTX only)
// ---------------------------------------------------------------------------
__device__ __forceinline__ uint32_t cvta_s(const void* p) {
    uint32_t a;
    asm("{ .reg .u64 t; cvta.to.shared.u64 t, %1; cvt.u32.u64 %0, t; }"
        : "=r"(a) : "l"(p));
    return a;
}

__device__ __forceinline__ void cp16(uint32_t dst, const void* src) {
    asm volatile("cp.async.cg.shared.global [%0], [%1], 16;"
                 :: "r"(dst), "l"(src) : "memory");
}

__device__ __forceinline__ void ldm4(uint32_t addr, uint32_t& r0, uint32_t& r1,
                                     uint32_t& r2, uint32_t& r3) {
    asm volatile("ldmatrix.sync.aligned.m8n8.x4.shared.b16 {%0,%1,%2,%3}, [%4];"
                 : "=r"(r0), "=r"(r1), "=r"(r2), "=r"(r3) : "r"(addr));
}

__device__ __forceinline__ void ldm4t(uint32_t addr, uint32_t& r0, uint32_t& r1,
                                      uint32_t& r2, uint32_t& r3) {
    asm volatile("ldmatrix.sync.aligned.m8n8.x4.trans.shared.b16 {%0,%1,%2,%3}, [%4];"
                 : "=r"(r0), "=r"(r1), "=r"(r2), "=r"(r3) : "r"(addr));
}

__device__ __forceinline__ void mma_bf16(float* d, const uint32_t* a,
                                         uint32_t b0, uint32_t b1) {
    asm volatile(
        "mma.sync.aligned.m16n8k16.row.col.f32.bf16.bf16.f32 "
        "{%0,%1,%2,%3}, {%4,%5,%6,%7}, {%8,%9}, {%0,%1,%2,%3};"
        : "+f"(d[0]), "+f"(d[1]), "+f"(d[2]), "+f"(d[3])
        : "r"(a[0]), "r"(a[1]), "r"(a[2]), "r"(a[3]), "r"(b0), "r"(b1));
}

__device__ __forceinline__ float ex2f(float x) {
    float y;
    asm("ex2.approx.f32 %0, %1;" : "=f"(y) : "f"(x));
    return y;
}

// pack {lo, hi} floats into bf16x2 (lo in low half)
__device__ __forceinline__ uint32_t packbf(float lo, float hi) {
    uint32_t r;
    asm("cvt.rn.bf16x2.f32 %0, %1, %2;" : "=r"(r) : "f"(hi), "f"(lo));
    return r;
}
// residual pack given hi-pack hp of (f0, f1)
__device__ __forceinline__ uint32_t packres(uint32_t hp, float f0, float f1) {
    float h0 = __uint_as_float(hp << 16);
    float h1 = __uint_as_float(hp & 0xffff0000u);
    return packbf(f0 - h0, f1 - h1);
}

// ---------------------------------------------------------------------------
// split fp32 -> bf16 hi + lo (flat arrays, for GEMM operands)
// ---------------------------------------------------------------------------
__global__ __launch_bounds__(256) void split_bf16(
    const float4* __restrict__ in, uint32_t* __restrict__ hi,
    uint32_t* __restrict__ lo, int n4)
{
    int i = blockIdx.x * blockDim.x + threadIdx.x;
    if (i >= n4) return;
    float4 v = in[i];
    uint32_t h0 = packbf(v.x, v.y), h1 = packbf(v.z, v.w);
    hi[2 * i] = h0; hi[2 * i + 1] = h1;
    lo[2 * i] = packres(h0, v.x, v.y);
    lo[2 * i + 1] = packres(h1, v.z, v.w);
}

// ---------------------------------------------------------------------------
// split qkv [b,t,3,h,d] fp32 -> q/k/v hi+lo bf16 in [b,h,t,d]
// ---------------------------------------------------------------------------
__global__ __launch_bounds__(256) void split_qkv(
    const float* __restrict__ qkv,
    __nv_bfloat16* __restrict__ qh, __nv_bfloat16* __restrict__ ql,
    __nv_bfloat16* __restrict__ kh, __nv_bfloat16* __restrict__ kl,
    __nv_bfloat16* __restrict__ vh, __nv_bfloat16* __restrict__ vl)
{
    const int bt = blockIdx.x;
    const int b = bt >> 12, t = bt & 4095;
    const float* src = qkv + (size_t)bt * 3072;
#pragma unroll
    for (int j = 0; j < 3; j++) {
        int idx = threadIdx.x + j * 256;   // float4 index 0..767
        int col = idx * 4;
        int type = col >> 10;
        int h = (col >> 6) & 15;
        int d = col & 63;
        float4 v = *(const float4*)(src + col);
        uint32_t h0 = packbf(v.x, v.y), h1 = packbf(v.z, v.w);
        uint32_t l0 = packres(h0, v.x, v.y), l1 = packres(h1, v.z, v.w);
        __nv_bfloat16* dh = (type == 0) ? qh : (type == 1) ? kh : vh;
        __nv_bfloat16* dl = (type == 0) ? ql : (type == 1) ? kl : vl;
        size_t o = ((size_t)(b * H_DIM + h) * T_DIM + t) * 64 + d;
        *(uint2*)(dh + o) = make_uint2(h0, h1);
        *(uint2*)(dl + o) = make_uint2(l0, l1);
    }
}

// ---------------------------------------------------------------------------
// 3-term split-bf16 GEMM (unchanged from R3)
// ---------------------------------------------------------------------------
#define PITCH   40
#define TILEB   (128 * PITCH * 2)
#define STAGEB  (4 * TILEB)
#define NSTAGE  3

__device__ __forceinline__ void ld_tile(const __nv_bfloat16* __restrict__ G,
                                        int K, int row0, int k0,
                                        uint32_t dstbase, int tid)
{
#pragma unroll
    for (int t = 0; t < 2; t++) {
        int idx = tid + t * 256;
        int r = idx >> 2;
        int c = idx & 3;
        cp16(dstbase + r * 80 + c * 16,
             G + (size_t)(row0 + r) * K + k0 + c * 8);
    }
}

__global__ __launch_bounds__(256) void gemm_bf16x3(
    const __nv_bfloat16* __restrict__ Ah, const __nv_bfloat16* __restrict__ Al,
    const __nv_bfloat16* __restrict__ Bh, const __nv_bfloat16* __restrict__ Bl,
    float* __restrict__ C, int N, int K)
{
    extern __shared__ __align__(128) char smraw[];
    const uint32_t smbase = cvta_s(smraw);

    const int tid  = threadIdx.x;
    const int wid  = tid >> 5;
    const int lane = tid & 31;
    const int n0 = blockIdx.x * 128;
    const int m0 = blockIdx.y * 128;
    const int wm = (wid & 1) * 64;
    const int wn = (wid >> 1) * 32;
    const int lr = lane & 15;
    const int lc = lane >> 4;

    float acc[4][4][4];
#pragma unroll
    for (int i = 0; i < 4; i++)
#pragma unroll
        for (int j = 0; j < 4; j++)
#pragma unroll
            for (int k = 0; k < 4; k++) acc[i][j][k] = 0.0f;

    const int nch = K / 32;

#pragma unroll
    for (int c = 0; c < NSTAGE; c++) {
        uint32_t sb = smbase + c * STAGEB;
        ld_tile(Ah, K, m0, c * 32, sb, tid);
        ld_tile(Al, K, m0, c * 32, sb + TILEB, tid);
        ld_tile(Bh, K, n0, c * 32, sb + 2 * TILEB, tid);
        ld_tile(Bl, K, n0, c * 32, sb + 3 * TILEB, tid);
        asm volatile("cp.async.commit_group;" ::: "memory");
    }

    for (int c = 0; c < nch; c++) {
        asm volatile("cp.async.wait_group %0;" :: "n"(NSTAGE - 1) : "memory");
        __syncthreads();

        uint32_t sb  = smbase + (c % NSTAGE) * STAGEB;
        uint32_t aHb = sb + (wm + lr) * 80;
        uint32_t aLb = aHb + TILEB;
        uint32_t bHb = sb + 2 * TILEB + (wn + lr) * 80;
        uint32_t bLb = bHb + TILEB;

#pragma unroll
        for (int ks = 0; ks < 2; ks++) {
            uint32_t koff = (ks * 2 + lc) * 16;
            uint32_t ah[4][4], al4[4][4];
#pragma unroll
            for (int mt = 0; mt < 4; mt++) {
                ldm4(aHb + mt * 16 * 80 + koff,
                     ah[mt][0], ah[mt][1], ah[mt][2], ah[mt][3]);
                ldm4(aLb + mt * 16 * 80 + koff,
                     al4[mt][0], al4[mt][1], al4[mt][2], al4[mt][3]);
            }
            uint32_t bh[2][4], bl[2][4];
#pragma unroll
            for (int p = 0; p < 2; p++) {
                ldm4(bHb + p * 16 * 80 + koff,
                     bh[p][0], bh[p][1], bh[p][2], bh[p][3]);
                ldm4(bLb + p * 16 * 80 + koff,
                     bl[p][0], bl[p][1], bl[p][2], bl[p][3]);
            }
#pragma unroll
            for (int mt = 0; mt < 4; mt++) {
#pragma unroll
                for (int nt = 0; nt < 4; nt++) {
                    const int p = nt >> 1, h = nt & 1;
                    mma_bf16(acc[mt][nt], ah[mt],  bh[p][h], bh[p][2 + h]);
                    mma_bf16(acc[mt][nt], al4[mt], bh[p][h], bh[p][2 + h]);
                    mma_bf16(acc[mt][nt], ah[mt],  bl[p][h], bl[p][2 + h]);
                }
            }
        }
        __syncthreads();

        if (c + NSTAGE < nch) {
            uint32_t db = smbase + (c % NSTAGE) * STAGEB;
            int kk = (c + NSTAGE) * 32;
            ld_tile(Ah, K, m0, kk, db, tid);
            ld_tile(Al, K, m0, kk, db + TILEB, tid);
            ld_tile(Bh, K, n0, kk, db + 2 * TILEB, tid);
            ld_tile(Bl, K, n0, kk, db + 3 * TILEB, tid);
        }
        asm volatile("cp.async.commit_group;" ::: "memory");
    }

    const int er = lane >> 2;
    const int ec = (lane & 3) * 2;
#pragma unroll
    for (int mt = 0; mt < 4; mt++) {
#pragma unroll
        for (int nt = 0; nt < 4; nt++) {
            size_t row = (size_t)(m0 + wm + mt * 16 + er);
            int col = n0 + wn + nt * 8 + ec;
            *(float2*)(C + row * N + col) =
                make_float2(acc[mt][nt][0], acc[mt][nt][1]);
            *(float2*)(C + (row + 8) * N + col) =
                make_float2(acc[mt][nt][2], acc[mt][nt][3]);
        }
    }
}

// ---------------------------------------------------------------------------
// Flash attention on mma.sync, split-bf16 3-term, causal.
// 128 threads (4 warps), Br=64 (16 rows/warp), Bc=64, double-buffered K/V.
// smem tiles 64 rows x 144B pitch.
// ---------------------------------------------------------------------------
#define AT_TILEB 9216        // 64 * 144

__device__ __forceinline__ void kload(
    const __nv_bfloat16* __restrict__ kh, const __nv_bfloat16* __restrict__ kl,
    const __nv_bfloat16* __restrict__ vh, const __nv_bfloat16* __restrict__ vl,
    size_t gbase, uint32_t st, int tid)
{
#pragma unroll
    for (int i = 0; i < 4; i++) {
        int idx = tid + i * 128;
        int r = idx >> 3, c = idx & 7;
        uint32_t d = st + r * 144 + c * 16;
        size_t g = gbase + (size_t)r * 64 + c * 8;
        cp16(d,                kh + g);
        cp16(d + AT_TILEB,     kl + g);
        cp16(d + 2 * AT_TILEB, vh + g);
        cp16(d + 3 * AT_TILEB, vl + g);
    }
}

__global__ __launch_bounds__(128) void attn_mma(
    const __nv_bfloat16* __restrict__ qh_, const __nv_bfloat16* __restrict__ ql_,
    const __nv_bfloat16* __restrict__ kh_, const __nv_bfloat16* __restrict__ kl_,
    const __nv_bfloat16* __restrict__ vh_, const __nv_bfloat16* __restrict__ vl_,
    __nv_bfloat16* __restrict__ ah_, __nv_bfloat16* __restrict__ al_)
{
    extern __shared__ __align__(128) char smraw2[];
    const uint32_t sb = cvta_s(smraw2);
    const int qt = gridDim.x - 1 - blockIdx.x;   // heavy tiles first
    const int h = blockIdx.y, b = blockIdx.z;
    const int tid = threadIdx.x, warp = tid >> 5, lane = tid & 31;
    const int q0 = qt * 64;
    const size_t head = (size_t)(b * H_DIM + h) * T_DIM;

    // ---- prologue: Q + stage0 (+stage1) loads ----
    {
        size_t g = (head + q0) * 64;
#pragma unroll
        for (int i = 0; i < 4; i++) {
            int idx = tid + i * 128;
            int r = idx >> 3, c = idx & 7;
            uint32_t d = sb + r * 144 + c * 16;
            cp16(d,            qh_ + g + (size_t)r * 64 + c * 8);
            cp16(d + AT_TILEB, ql_ + g + (size_t)r * 64 + c * 8);
        }
        kload(kh_, kl_, vh_, vl_, head * 64, sb + 2 * AT_TILEB, tid);
        asm volatile("cp.async.commit_group;" ::: "memory");
        if (qt >= 1) {
            kload(kh_, kl_, vh_, vl_, (head + 64) * 64, sb + 6 * AT_TILEB, tid);
            asm volatile("cp.async.commit_group;" ::: "memory");
            asm volatile("cp.async.wait_group 1;" ::: "memory");
        } else {
            asm volatile("cp.async.wait_group 0;" ::: "memory");
        }
    }
    __syncthreads();

    // ---- Q fragments (A-frags for 4 k16 steps), hi and lo ----
    uint32_t qf[4][4], qg[4][4];
    {
        uint32_t base = sb + (warp * 16 + (lane & 15)) * 144 + (lane >> 4) * 16;
#pragma unroll
        for (int ks = 0; ks < 4; ks++) {
            ldm4(base + ks * 32, qf[ks][0], qf[ks][1], qf[ks][2], qf[ks][3]);
            ldm4(base + AT_TILEB + ks * 32,
                 qg[ks][0], qg[ks][1], qg[ks][2], qg[ks][3]);
        }
    }

    float m0 = -1e30f, m1 = -1e30f, l0 = 0.0f, l1 = 0.0f;
    float o[8][4];
#pragma unroll
    for (int i = 0; i < 8; i++)
#pragma unroll
        for (int j = 0; j < 4; j++) o[i][j] = 0.0f;

    const float SC = 0.180336880f;   // 0.125 * log2(e)

    for (int kt = 0; kt <= qt; kt++) {
        if (kt > 0) {
            if (kt < qt)
                asm volatile("cp.async.wait_group 1;" ::: "memory");
            else
                asm volatile("cp.async.wait_group 0;" ::: "memory");
            __syncthreads();
        }
        const uint32_t st = sb + (2 + (kt & 1) * 4) * AT_TILEB;

        // ---- S = Q K^T (3-term) ----
        float s[8][4];
#pragma unroll
        for (int i = 0; i < 8; i++)
#pragma unroll
            for (int j = 0; j < 4; j++) s[i][j] = 0.0f;

        {
            uint32_t kb = st + (lane & 15) * 144 + (lane >> 4) * 16;
#pragma unroll
            for (int ks = 0; ks < 4; ks++) {
#pragma unroll
                for (int ng = 0; ng < 4; ng++) {
                    uint32_t a = kb + ng * 16 * 144 + ks * 32;
                    uint32_t h0, h1, h2, h3, g0, g1, g2, g3;
                    ldm4(a, h0, h1, h2, h3);
                    ldm4(a + AT_TILEB, g0, g1, g2, g3);
                    mma_bf16(s[2 * ng],     qf[ks], h0, h2);
                    mma_bf16(s[2 * ng],     qg[ks], h0, h2);
                    mma_bf16(s[2 * ng],     qf[ks], g0, g2);
                    mma_bf16(s[2 * ng + 1], qf[ks], h1, h3);
                    mma_bf16(s[2 * ng + 1], qg[ks], h1, h3);
                    mma_bf16(s[2 * ng + 1], qf[ks], g1, g3);
                }
            }
        }

        // ---- causal mask (diagonal tile only) ----
        if (kt == qt) {
            const int rb = warp * 16 + (lane >> 2);
            const int cb = (lane & 3) * 2;
#pragma unroll
            for (int nt = 0; nt < 8; nt++) {
                int c0 = nt * 8 + cb;
                if (c0     > rb)     s[nt][0] = -1e30f;
                if (c0 + 1 > rb)     s[nt][1] = -1e30f;
                if (c0     > rb + 8) s[nt][2] = -1e30f;
                if (c0 + 1 > rb + 8) s[nt][3] = -1e30f;
            }
        }

        // ---- online softmax (base-2, scale folded) ----
        float mx0 = s[0][0], mx1 = s[0][2];
#pragma unroll
        for (int nt = 0; nt < 8; nt++) {
            mx0 = fmaxf(mx0, fmaxf(s[nt][0], s[nt][1]));
            mx1 = fmaxf(mx1, fmaxf(s[nt][2], s[nt][3]));
        }
        mx0 = fmaxf(mx0, __shfl_xor_sync(0xffffffffu, mx0, 1));
        mx0 = fmaxf(mx0, __shfl_xor_sync(0xffffffffu, mx0, 2));
        mx1 = fmaxf(mx1, __shfl_xor_sync(0xffffffffu, mx1, 1));
        mx1 = fmaxf(mx1, __shfl_xor_sync(0xffffffffu, mx1, 2));

        float mn0 = fmaxf(m0, mx0), mn1 = fmaxf(m1, mx1);
        float a0 = ex2f((m0 - mn0) * SC), a1 = ex2f((m1 - mn1) * SC);
        m0 = mn0; m1 = mn1;

        float rs0 = 0.0f, rs1 = 0.0f;
#pragma unroll
        for (int nt = 0; nt < 8; nt++) {
            s[nt][0] = ex2f((s[nt][0] - mn0) * SC);
            s[nt][1] = ex2f((s[nt][1] - mn0) * SC);
            s[nt][2] = ex2f((s[nt][2] - mn1) * SC);
            s[nt][3] = ex2f((s[nt][3] - mn1) * SC);
            rs0 += s[nt][0] + s[nt][1];
            rs1 += s[nt][2] + s[nt][3];
        }
        rs0 += __shfl_xor_sync(0xffffffffu, rs0, 1);
        rs0 += __shfl_xor_sync(0xffffffffu, rs0, 2);
        rs1 += __shfl_xor_sync(0xffffffffu, rs1, 1);
        rs1 += __shfl_xor_sync(0xffffffffu, rs1, 2);
        l0 = l0 * a0 + rs0;
        l1 = l1 * a1 + rs1;

#pragma unroll
        for (int i = 0; i < 8; i++) {
            o[i][0] *= a0; o[i][1] *= a0;
            o[i][2] *= a1; o[i][3] *= a1;
        }

        // ---- O += P V (3-term), V via ldmatrix.trans ----
        {
            uint32_t vb = st + 2 * AT_TILEB + (lane & 15) * 144 + (lane >> 4) * 16;
#pragma unroll
            for (int ks2 = 0; ks2 < 4; ks2++) {
                uint32_t pa[4], pb[4];
                pa[0] = packbf(s[2 * ks2][0],     s[2 * ks2][1]);
                pa[1] = packbf(s[2 * ks2][2],     s[2 * ks2][3]);
                pa[2] = packbf(s[2 * ks2 + 1][0], s[2 * ks2 + 1][1]);
                pa[3] = packbf(s[2 * ks2 + 1][2], s[2 * ks2 + 1][3]);
                pb[0] = packres(pa[0], s[2 * ks2][0],     s[2 * ks2][1]);
                pb[1] = packres(pa[1], s[2 * ks2][2],     s[2 * ks2][3]);
                pb[2] = packres(pa[2], s[2 * ks2 + 1][0], s[2 * ks2 + 1][1]);
                pb[3] = packres(pa[3], s[2 * ks2 + 1][2], s[2 * ks2 + 1][3]);

                uint32_t rowoff = ks2 * 16 * 144;
#pragma unroll
                for (int dg = 0; dg < 4; dg++) {
                    uint32_t a = vb + rowoff + dg * 32;
                    uint32_t v0, v1, v2, v3, w0, w1, w2, w3;
                    ldm4t(a, v0, v1, v2, v3);
                    ldm4t(a + AT_TILEB, w0, w1, w2, w3);
                    mma_bf16(o[2 * dg],     pa, v0, v1);
                    mma_bf16(o[2 * dg],     pb, v0, v1);
                    mma_bf16(o[2 * dg],     pa, w0, w1);
                    mma_bf16(o[2 * dg + 1], pa, v2, v3);
                    mma_bf16(o[2 * dg + 1], pb, v2, v3);
                    mma_bf16(o[2 * dg + 1], pa, w2, w3);
                }
            }
        }
        __syncthreads();
        if (kt + 2 <= qt) {
            kload(kh_, kl_, vh_, vl_, (head + (size_t)(kt + 2) * 64) * 64, st, tid);
            asm volatile("cp.async.commit_group;" ::: "memory");
        }
    }

    // ---- epilogue: normalize, write bf16 hi/lo [b,t,C] ----
    const float i0 = 1.0f / l0, i1 = 1.0f / l1;
    const int row = q0 + warp * 16 + (lane >> 2);
    const size_t ob = ((size_t)b * T_DIM + row) * C_DIM + h * 64 + (lane & 3) * 2;
#pragma unroll
    for (int dnt = 0; dnt < 8; dnt++) {
        float v0 = o[dnt][0] * i0, v1 = o[dnt][1] * i0;
        uint32_t hp = packbf(v0, v1);
        *(uint32_t*)(ah_ + ob + dnt * 8) = hp;
        *(uint32_t*)(al_ + ob + dnt * 8) = packres(hp, v0, v1);
        float u0 = o[dnt][2] * i1, u1 = o[dnt][3] * i1;
        uint32_t hq = packbf(u0, u1);
        *(uint32_t*)(ah_ + ob + 8 * C_DIM + dnt * 8) = hq;
        *(uint32_t*)(al_ + ob + 8 * C_DIM + dnt * 8) = packres(hq, u0, u1);
    }
}

// ---------------------------------------------------------------------------
// launch
// ---------------------------------------------------------------------------
extern "C" void kernel_launch(void* const* d_in, const int* in_sizes, int n_in,
                              void* d_out, int out_size)
{
    const float* x    = (const float*)d_in[0];
    const float* wqkv = (const float*)d_in[1];
    const float* wout = (const float*)d_in[2];
    float* out = (float*)d_out;

    float* qkv;
    __nv_bfloat16 *xh, *xl, *wqh, *wql, *woh, *wol, *ah, *al;
    __nv_bfloat16 *qh2, *ql2, *kh2, *kl2, *vh2, *vl2;
    cudaGetSymbolAddress((void**)&qkv, g_qkv);
    cudaGetSymbolAddress((void**)&xh, g_xh);
    cudaGetSymbolAddress((void**)&xl, g_xl);
    cudaGetSymbolAddress((void**)&wqh, g_wqh);
    cudaGetSymbolAddress((void**)&wql, g_wql);
    cudaGetSymbolAddress((void**)&woh, g_woh);
    cudaGetSymbolAddress((void**)&wol, g_wol);
    cudaGetSymbolAddress((void**)&ah, g_ah);
    cudaGetSymbolAddress((void**)&al, g_al);
    cudaGetSymbolAddress((void**)&qh2, g_qh2);
    cudaGetSymbolAddress((void**)&ql2, g_ql2);
    cudaGetSymbolAddress((void**)&kh2, g_kh2);
    cudaGetSymbolAddress((void**)&kl2, g_kl2);
    cudaGetSymbolAddress((void**)&vh2, g_vh2);
    cudaGetSymbolAddress((void**)&vl2, g_vl2);

    const int gemm_smem = NSTAGE * STAGEB;   // 122880
    cudaFuncSetAttribute(gemm_bf16x3, cudaFuncAttributeMaxDynamicSharedMemorySize,
                         gemm_smem);
    const int attn_smem = 10 * AT_TILEB;     // 92160
    cudaFuncSetAttribute(attn_mma, cudaFuncAttributeMaxDynamicSharedMemorySize,
                         attn_smem);

    // split inputs to bf16 hi/lo
    {
        int n4 = MROWS * KDIM / 4;
        split_bf16<<<(n4 + 255) / 256, 256>>>((const float4*)x,
            (uint32_t*)xh, (uint32_t*)xl, n4);
        n4 = 3 * C_DIM * KDIM / 4;
        split_bf16<<<(n4 + 255) / 256, 256>>>((const float4*)wqkv,
            (uint32_t*)wqh, (uint32_t*)wql, n4);
        n4 = C_DIM * KDIM / 4;
        split_bf16<<<(n4 + 255) / 256, 256>>>((const float4*)wout,
            (uint32_t*)woh, (uint32_t*)wol, n4);
    }

    // 1) QKV projection: [8192, 3072] fp32
    gemm_bf16x3<<<dim3(3 * C_DIM / 128, MROWS / 128), 256, gemm_smem>>>(
        xh, xl, wqh, wql, qkv, 3 * C_DIM, KDIM);

    // 1b) split qkv into per-head bf16 hi/lo [b,h,t,d]
    split_qkv<<<MROWS, 256>>>(qkv, qh2, ql2, kh2, kl2, vh2, vl2);

    // 2) flash attention (tensor-core), writes bf16 hi/lo att
    attn_mma<<<dim3(T_DIM / 64, H_DIM, B_DIM), 128, attn_smem>>>(
        qh2, ql2, kh2, kl2, vh2, vl2, ah, al);

    // 3) output projection: [8192, 1024]
    gemm_bf16x3<<<dim3(C_DIM / 128, MROWS / 128), 256, gemm_smem>>>(
        ah, al, woh, wol, out, C_DIM, KDIM);
}

// round 5
// speedup vs baseline: 2.8023x; 1.1489x over previous
#include <cuda_runtime.h>
#include <cuda_bf16.h>
#include <cstdint>

#define B_DIM 2
#define T_DIM 4096
#define C_DIM 1024
#define H_DIM 16
#define D_DIM 64
#define MROWS (B_DIM * T_DIM)   // 8192
#define KDIM  C_DIM             // 1024

// ---------------- static device scratch (no allocs allowed) ----------------
__device__ float g_qkv[(size_t)MROWS * 3 * C_DIM];   // [B,T,3,H,D]

__device__ __align__(256) __nv_bfloat16 g_xh[(size_t)MROWS * KDIM];
__device__ __align__(256) __nv_bfloat16 g_xl[(size_t)MROWS * KDIM];
__device__ __align__(256) __nv_bfloat16 g_wqh[(size_t)3 * C_DIM * KDIM];
__device__ __align__(256) __nv_bfloat16 g_wql[(size_t)3 * C_DIM * KDIM];
__device__ __align__(256) __nv_bfloat16 g_woh[(size_t)C_DIM * KDIM];
__device__ __align__(256) __nv_bfloat16 g_wol[(size_t)C_DIM * KDIM];
__device__ __align__(256) __nv_bfloat16 g_ah[(size_t)MROWS * KDIM];
__device__ __align__(256) __nv_bfloat16 g_al[(size_t)MROWS * KDIM];

// per-head [b,h,t,d] bf16 hi/lo for attention
__device__ __align__(256) __nv_bfloat16 g_qh2[(size_t)MROWS * C_DIM];
__device__ __align__(256) __nv_bfloat16 g_ql2[(size_t)MROWS * C_DIM];
__device__ __align__(256) __nv_bfloat16 g_kh2[(size_t)MROWS * C_DIM];
__device__ __align__(256) __nv_bfloat16 g_kl2[(size_t)MROWS * C_DIM];
__device__ __align__(256) __nv_bfloat16 g_vh2[(size_t)MROWS * C_DIM];
__device__ __align__(256) __nv_bfloat16 g_vl2[(size_t)MROWS * C_DIM];

// ---------------------------------------------------------------------------
// PTX helpers
// ---------------------------------------------------------------------------
__device__ __forceinline__ uint32_t cvta_s(const void* p) {
    uint32_t a;
    asm("{ .reg .u64 t; cvta.to.shared.u64 t, %1; cvt.u32.u64 %0, t; }"
        : "=r"(a) : "l"(p));
    return a;
}

__device__ __forceinline__ void cp16(uint32_t dst, const void* src) {
    asm volatile("cp.async.cg.shared.global [%0], [%1], 16;"
                 :: "r"(dst), "l"(src) : "memory");
}

__device__ __forceinline__ void ldm4(uint32_t addr, uint32_t& r0, uint32_t& r1,
                                     uint32_t& r2, uint32_t& r3) {
    asm volatile("ldmatrix.sync.aligned.m8n8.x4.shared.b16 {%0,%1,%2,%3}, [%4];"
                 : "=r"(r0), "=r"(r1), "=r"(r2), "=r"(r3) : "r"(addr));
}

__device__ __forceinline__ void ldm4t(uint32_t addr, uint32_t& r0, uint32_t& r1,
                                      uint32_t& r2, uint32_t& r3) {
    asm volatile("ldmatrix.sync.aligned.m8n8.x4.trans.shared.b16 {%0,%1,%2,%3}, [%4];"
                 : "=r"(r0), "=r"(r1), "=r"(r2), "=r"(r3) : "r"(addr));
}

__device__ __forceinline__ void mma_bf16(float* d, const uint32_t* a,
                                         uint32_t b0, uint32_t b1) {
    asm volatile(
        "mma.sync.aligned.m16n8k16.row.col.f32.bf16.bf16.f32 "
        "{%0,%1,%2,%3}, {%4,%5,%6,%7}, {%8,%9}, {%0,%1,%2,%3};"
        : "+f"(d[0]), "+f"(d[1]), "+f"(d[2]), "+f"(d[3])
        : "r"(a[0]), "r"(a[1]), "r"(a[2]), "r"(a[3]), "r"(b0), "r"(b1));
}

__device__ __forceinline__ float ex2f(float x) {
    float y;
    asm("ex2.approx.f32 %0, %1;" : "=f"(y) : "f"(x));
    return y;
}

__device__ __forceinline__ uint32_t packbf(float lo, float hi) {
    uint32_t r;
    asm("cvt.rn.bf16x2.f32 %0, %1, %2;" : "=r"(r) : "f"(hi), "f"(lo));
    return r;
}
__device__ __forceinline__ uint32_t packres(uint32_t hp, float f0, float f1) {
    float h0 = __uint_as_float(hp << 16);
    float h1 = __uint_as_float(hp & 0xffff0000u);
    return packbf(f0 - h0, f1 - h1);
}

// SW128: row r (128B rows), 16B chunk c(0..7) -> byte offset
__device__ __forceinline__ uint32_t swz(uint32_t r, uint32_t c) {
    return r * 128 + ((c ^ (r & 7)) << 4);
}

// ---------------------------------------------------------------------------
// split kernels
// ---------------------------------------------------------------------------
__global__ __launch_bounds__(256) void split_bf16(
    const float4* __restrict__ in, uint32_t* __restrict__ hi,
    uint32_t* __restrict__ lo, int n4)
{
    int i = blockIdx.x * blockDim.x + threadIdx.x;
    if (i >= n4) return;
    float4 v = in[i];
    uint32_t h0 = packbf(v.x, v.y), h1 = packbf(v.z, v.w);
    hi[2 * i] = h0; hi[2 * i + 1] = h1;
    lo[2 * i] = packres(h0, v.x, v.y);
    lo[2 * i + 1] = packres(h1, v.z, v.w);
}

__global__ __launch_bounds__(256) void split_qkv(
    const float* __restrict__ qkv,
    __nv_bfloat16* __restrict__ qh, __nv_bfloat16* __restrict__ ql,
    __nv_bfloat16* __restrict__ kh, __nv_bfloat16* __restrict__ kl,
    __nv_bfloat16* __restrict__ vh, __nv_bfloat16* __restrict__ vl)
{
    const int bt = blockIdx.x;
    const int b = bt >> 12, t = bt & 4095;
    const float* src = qkv + (size_t)bt * 3072;
#pragma unroll
    for (int j = 0; j < 3; j++) {
        int idx = threadIdx.x + j * 256;
        int col = idx * 4;
        int type = col >> 10;
        int h = (col >> 6) & 15;
        int d = col & 63;
        float4 v = *(const float4*)(src + col);
        uint32_t h0 = packbf(v.x, v.y), h1 = packbf(v.z, v.w);
        uint32_t l0 = packres(h0, v.x, v.y), l1 = packres(h1, v.z, v.w);
        __nv_bfloat16* dh = (type == 0) ? qh : (type == 1) ? kh : vh;
        __nv_bfloat16* dl = (type == 0) ? ql : (type == 1) ? kl : vl;
        size_t o = ((size_t)(b * H_DIM + h) * T_DIM + t) * 64 + d;
        *(uint2*)(dh + o) = make_uint2(h0, h1);
        *(uint2*)(dl + o) = make_uint2(l0, l1);
    }
}

// ---------------------------------------------------------------------------
// 3-term split-bf16 GEMM, SW128-swizzled smem (hi|lo interleaved in 128B rows)
// CTA 128x128, BK=32, 3 stages x 32KB = 96KB -> 2 CTAs/SM
// ---------------------------------------------------------------------------
#define GTILE   16384       // combined (hi|lo) 128x32 tile: 128 rows x 128B
#define GSTAGE  32768       // A + B combined tiles
#define GNSTAGE 3

// load combined hi|lo tile: chunks 0-3 = hi, 4-7 = lo
__device__ __forceinline__ void g_ldtile(
    const __nv_bfloat16* __restrict__ Gh, const __nv_bfloat16* __restrict__ Gl,
    int K, int row0, int k0, uint32_t base, int tid)
{
#pragma unroll
    for (int t = 0; t < 4; t++) {
        int idx = tid + t * 256;           // 0..1023
        int r = idx >> 3, c = idx & 7;
        const __nv_bfloat16* src = (c < 4)
            ? Gh + (size_t)(row0 + r) * K + k0 + c * 8
            : Gl + (size_t)(row0 + r) * K + k0 + (c - 4) * 8;
        cp16(base + swz(r, c), src);
    }
}

__global__ __launch_bounds__(256, 2) void gemm_bf16x3(
    const __nv_bfloat16* __restrict__ Ah, const __nv_bfloat16* __restrict__ Al,
    const __nv_bfloat16* __restrict__ Bh, const __nv_bfloat16* __restrict__ Bl,
    float* __restrict__ C, int N, int K)
{
    extern __shared__ __align__(128) char smraw[];
    const uint32_t smbase = cvta_s(smraw);

    const int tid  = threadIdx.x;
    const int wid  = tid >> 5;
    const int lane = tid & 31;
    const int n0 = blockIdx.x * 128;
    const int m0 = blockIdx.y * 128;
    const int wm = (wid & 1) * 64;
    const int wn = (wid >> 1) * 32;
    const int lr = lane & 15;
    const int lc = lane >> 4;

    float acc[4][4][4];
#pragma unroll
    for (int i = 0; i < 4; i++)
#pragma unroll
        for (int j = 0; j < 4; j++)
#pragma unroll
            for (int k = 0; k < 4; k++) acc[i][j][k] = 0.0f;

    const int nch = K / 32;

#pragma unroll
    for (int c = 0; c < GNSTAGE; c++) {
        uint32_t sb = smbase + c * GSTAGE;
        g_ldtile(Ah, Al, K, m0, c * 32, sb, tid);
        g_ldtile(Bh, Bl, K, n0, c * 32, sb + GTILE, tid);
        asm volatile("cp.async.commit_group;" ::: "memory");
    }

    for (int c = 0; c < nch; c++) {
        asm volatile("cp.async.wait_group %0;" :: "n"(GNSTAGE - 1) : "memory");
        __syncthreads();

        uint32_t sb = smbase + (c % GNSTAGE) * GSTAGE;

#pragma unroll
        for (int ks = 0; ks < 2; ks++) {
            const uint32_t ch = ks * 2 + lc;       // hi chunk
            uint32_t ah[4][4], al4[4][4];
#pragma unroll
            for (int mt = 0; mt < 4; mt++) {
                uint32_t row = wm + mt * 16 + lr;
                uint32_t rb = sb + row * 128;
                uint32_t key = row & 7;
                ldm4(rb + ((ch ^ key) << 4),
                     ah[mt][0], ah[mt][1], ah[mt][2], ah[mt][3]);
                ldm4(rb + (((ch + 4) ^ key) << 4),
                     al4[mt][0], al4[mt][1], al4[mt][2], al4[mt][3]);
            }
            uint32_t bh[2][4], bl[2][4];
#pragma unroll
            for (int p = 0; p < 2; p++) {
                uint32_t row = wn + p * 16 + lr;
                uint32_t rb = sb + GTILE + row * 128;
                uint32_t key = row & 7;
                ldm4(rb + ((ch ^ key) << 4),
                     bh[p][0], bh[p][1], bh[p][2], bh[p][3]);
                ldm4(rb + (((ch + 4) ^ key) << 4),
                     bl[p][0], bl[p][1], bl[p][2], bl[p][3]);
            }
#pragma unroll
            for (int mt = 0; mt < 4; mt++) {
#pragma unroll
                for (int nt = 0; nt < 4; nt++) {
                    const int p = nt >> 1, h = nt & 1;
                    mma_bf16(acc[mt][nt], ah[mt],  bh[p][h], bh[p][2 + h]);
                    mma_bf16(acc[mt][nt], al4[mt], bh[p][h], bh[p][2 + h]);
                    mma_bf16(acc[mt][nt], ah[mt],  bl[p][h], bl[p][2 + h]);
                }
            }
        }
        __syncthreads();

        if (c + GNSTAGE < nch) {
            uint32_t db = smbase + (c % GNSTAGE) * GSTAGE;
            int kk = (c + GNSTAGE) * 32;
            g_ldtile(Ah, Al, K, m0, kk, db, tid);
            g_ldtile(Bh, Bl, K, n0, kk, db + GTILE, tid);
        }
        asm volatile("cp.async.commit_group;" ::: "memory");
    }

    const int er = lane >> 2;
    const int ec = (lane & 3) * 2;
#pragma unroll
    for (int mt = 0; mt < 4; mt++) {
#pragma unroll
        for (int nt = 0; nt < 4; nt++) {
            size_t row = (size_t)(m0 + wm + mt * 16 + er);
            int col = n0 + wn + nt * 8 + ec;
            *(float2*)(C + row * N + col) =
                make_float2(acc[mt][nt][0], acc[mt][nt][1]);
            *(float2*)(C + (row + 8) * N + col) =
                make_float2(acc[mt][nt][2], acc[mt][nt][3]);
        }
    }
}

// ---------------------------------------------------------------------------
// Flash attention on mma.sync, split-bf16, causal.
// Br=128 (8 warps x 16 rows), Bc=64, SW128 smem, 96KB -> 2 CTAs/SM.
// ---------------------------------------------------------------------------
#define AQT 16384                 // one 128x64 Q tile (hi or lo)
#define AKT 8192                  // one 64x64 K/V tile
#define AST 32768                 // K/V stage: Kh|Kl|Vh|Vl
#define ASOFF 32768               // stages start after Qh|Ql

__device__ __forceinline__ void kload(
    const __nv_bfloat16* __restrict__ kh, const __nv_bfloat16* __restrict__ kl,
    const __nv_bfloat16* __restrict__ vh, const __nv_bfloat16* __restrict__ vl,
    size_t gbase, uint32_t st, int tid)
{
    const __nv_bfloat16* ptrs[4] = {kh, kl, vh, vl};
#pragma unroll
    for (int t = 0; t < 8; t++) {
        int idx = tid + t * 256;            // 0..2047
        int tile = idx >> 9;
        int rem = idx & 511;
        int r = rem >> 3, c = rem & 7;
        cp16(st + tile * AKT + swz(r, c),
             ptrs[tile] + gbase + (size_t)r * 64 + c * 8);
    }
}

__global__ __launch_bounds__(256, 2) void attn_mma(
    const __nv_bfloat16* __restrict__ qh_, const __nv_bfloat16* __restrict__ ql_,
    const __nv_bfloat16* __restrict__ kh_, const __nv_bfloat16* __restrict__ kl_,
    const __nv_bfloat16* __restrict__ vh_, const __nv_bfloat16* __restrict__ vl_,
    __nv_bfloat16* __restrict__ ah_, __nv_bfloat16* __restrict__ al_)
{
    extern __shared__ __align__(128) char smraw2[];
    const uint32_t sb = cvta_s(smraw2);
    const int qt = gridDim.x - 1 - blockIdx.x;   // heavy tiles first
    const int h = blockIdx.y, b = blockIdx.z;
    const int tid = threadIdx.x, warp = tid >> 5, lane = tid & 31;
    const int q0 = qt * 128;
    const size_t head = (size_t)(b * H_DIM + h) * T_DIM;
    const int nkt = 2 * qt + 2;
    const int lr = lane & 15, lc = lane >> 4;

    // ---- prologue: Q (hi/lo) + stage0 + stage1 ----
    {
        size_t g = (head + q0) * 64;
#pragma unroll
        for (int t = 0; t < 8; t++) {
            int idx = tid + t * 256;        // 0..2047
            int tile = idx >> 10;           // 0=hi 1=lo
            int rem = idx & 1023;
            int r = rem >> 3, c = rem & 7;
            cp16(sb + tile * AQT + swz(r, c),
                 (tile ? ql_ : qh_) + g + (size_t)r * 64 + c * 8);
        }
        kload(kh_, kl_, vh_, vl_, head * 64, sb + ASOFF, tid);
        asm volatile("cp.async.commit_group;" ::: "memory");
        kload(kh_, kl_, vh_, vl_, (head + 64) * 64, sb + ASOFF + AST, tid);
        asm volatile("cp.async.commit_group;" ::: "memory");
        asm volatile("cp.async.wait_group 1;" ::: "memory");
    }
    __syncthreads();

    // ---- Q fragments ----
    uint32_t qf[4][4], qg[4][4];
    {
        uint32_t row = warp * 16 + lr;
        uint32_t rb = sb + row * 128;
        uint32_t key = row & 7;
#pragma unroll
        for (int ks = 0; ks < 4; ks++) {
            uint32_t ch = ks * 2 + lc;
            ldm4(rb + (((ch) ^ key) << 4),
                 qf[ks][0], qf[ks][1], qf[ks][2], qf[ks][3]);
            ldm4(rb + AQT + ((ch ^ key) << 4),
                 qg[ks][0], qg[ks][1], qg[ks][2], qg[ks][3]);
        }
    }

    float m0 = -1e30f, m1 = -1e30f, l0 = 0.0f, l1 = 0.0f;
    float o[8][4];
#pragma unroll
    for (int i = 0; i < 8; i++)
#pragma unroll
        for (int j = 0; j < 4; j++) o[i][j] = 0.0f;

    const float SC = 0.180336880f;   // 0.125 * log2(e)
    const int grow = q0 + warp * 16; // warp's first row

    for (int kt = 0; kt < nkt; kt++) {
        if (kt > 0) {
            if (kt < nkt - 1)
                asm volatile("cp.async.wait_group 1;" ::: "memory");
            else
                asm volatile("cp.async.wait_group 0;" ::: "memory");
            __syncthreads();
        }
        const uint32_t st = sb + ASOFF + (kt & 1) * AST;

        // ---- S = Q K^T (3-term) ----
        float s[8][4];
#pragma unroll
        for (int i = 0; i < 8; i++)
#pragma unroll
            for (int j = 0; j < 4; j++) s[i][j] = 0.0f;

#pragma unroll
        for (int ks = 0; ks < 4; ks++) {
            uint32_t ch = ks * 2 + lc;
#pragma unroll
            for (int ng = 0; ng < 4; ng++) {
                uint32_t row = ng * 16 + lr;
                uint32_t rb = st + row * 128;
                uint32_t key = row & 7;
                uint32_t h0, h1, h2, h3, g0, g1, g2, g3;
                ldm4(rb + ((ch ^ key) << 4), h0, h1, h2, h3);
                ldm4(rb + AKT + ((ch ^ key) << 4), g0, g1, g2, g3);
                mma_bf16(s[2 * ng],     qf[ks], h0, h2);
                mma_bf16(s[2 * ng],     qg[ks], h0, h2);
                mma_bf16(s[2 * ng],     qf[ks], g0, g2);
                mma_bf16(s[2 * ng + 1], qf[ks], h1, h3);
                mma_bf16(s[2 * ng + 1], qg[ks], h1, h3);
                mma_bf16(s[2 * ng + 1], qf[ks], g1, g3);
            }
        }

        // ---- causal mask ----
        if (kt * 64 + 63 > grow) {
            const int rb0 = grow + (lane >> 2);
            const int cb = kt * 64 + (lane & 3) * 2;
#pragma unroll
            for (int nt = 0; nt < 8; nt++) {
                int c0 = cb + nt * 8;
                if (c0     > rb0)     s[nt][0] = -1e30f;
                if (c0 + 1 > rb0)     s[nt][1] = -1e30f;
                if (c0     > rb0 + 8) s[nt][2] = -1e30f;
                if (c0 + 1 > rb0 + 8) s[nt][3] = -1e30f;
            }
        }

        // ---- online softmax (base-2) ----
        float mx0 = s[0][0], mx1 = s[0][2];
#pragma unroll
        for (int nt = 0; nt < 8; nt++) {
            mx0 = fmaxf(mx0, fmaxf(s[nt][0], s[nt][1]));
            mx1 = fmaxf(mx1, fmaxf(s[nt][2], s[nt][3]));
        }
        mx0 = fmaxf(mx0, __shfl_xor_sync(0xffffffffu, mx0, 1));
        mx0 = fmaxf(mx0, __shfl_xor_sync(0xffffffffu, mx0, 2));
        mx1 = fmaxf(mx1, __shfl_xor_sync(0xffffffffu, mx1, 1));
        mx1 = fmaxf(mx1, __shfl_xor_sync(0xffffffffu, mx1, 2));

        float mn0 = fmaxf(m0, mx0), mn1 = fmaxf(m1, mx1);
        float a0 = ex2f((m0 - mn0) * SC), a1 = ex2f((m1 - mn1) * SC);
        m0 = mn0; m1 = mn1;

        float rs0 = 0.0f, rs1 = 0.0f;
#pragma unroll
        for (int nt = 0; nt < 8; nt++) {
            s[nt][0] = ex2f((s[nt][0] - mn0) * SC);
            s[nt][1] = ex2f((s[nt][1] - mn0) * SC);
            s[nt][2] = ex2f((s[nt][2] - mn1) * SC);
            s[nt][3] = ex2f((s[nt][3] - mn1) * SC);
            rs0 += s[nt][0] + s[nt][1];
            rs1 += s[nt][2] + s[nt][3];
        }
        rs0 += __shfl_xor_sync(0xffffffffu, rs0, 1);
        rs0 += __shfl_xor_sync(0xffffffffu, rs0, 2);
        rs1 += __shfl_xor_sync(0xffffffffu, rs1, 1);
        rs1 += __shfl_xor_sync(0xffffffffu, rs1, 2);
        l0 = l0 * a0 + rs0;
        l1 = l1 * a1 + rs1;

#pragma unroll
        for (int i = 0; i < 8; i++) {
            o[i][0] *= a0; o[i][1] *= a0;
            o[i][2] *= a1; o[i][3] *= a1;
        }

        // ---- O += P V (3-term) ----
#pragma unroll
        for (int ks2 = 0; ks2 < 4; ks2++) {
            uint32_t pa[4], pb[4];
            pa[0] = packbf(s[2 * ks2][0],     s[2 * ks2][1]);
            pa[1] = packbf(s[2 * ks2][2],     s[2 * ks2][3]);
            pa[2] = packbf(s[2 * ks2 + 1][0], s[2 * ks2 + 1][1]);
            pa[3] = packbf(s[2 * ks2 + 1][2], s[2 * ks2 + 1][3]);
            pb[0] = packres(pa[0], s[2 * ks2][0],     s[2 * ks2][1]);
            pb[1] = packres(pa[1], s[2 * ks2][2],     s[2 * ks2][3]);
            pb[2] = packres(pa[2], s[2 * ks2 + 1][0], s[2 * ks2 + 1][1]);
            pb[3] = packres(pa[3], s[2 * ks2 + 1][2], s[2 * ks2 + 1][3]);

            uint32_t row = ks2 * 16 + lr;
            uint32_t rb = st + 2 * AKT + row * 128;
            uint32_t key = row & 7;
#pragma unroll
            for (int dg = 0; dg < 4; dg++) {
                uint32_t ch = dg * 2 + lc;
                uint32_t a = rb + ((ch ^ key) << 4);
                uint32_t v0, v1, v2, v3, w0, w1, w2, w3;
                ldm4t(a, v0, v1, v2, v3);
                ldm4t(a + AKT, w0, w1, w2, w3);
                mma_bf16(o[2 * dg],     pa, v0, v1);
                mma_bf16(o[2 * dg],     pb, v0, v1);
                mma_bf16(o[2 * dg],     pa, w0, w1);
                mma_bf16(o[2 * dg + 1], pa, v2, v3);
                mma_bf16(o[2 * dg + 1], pb, v2, v3);
                mma_bf16(o[2 * dg + 1], pa, w2, w3);
            }
        }
        __syncthreads();
        if (kt + 2 < nkt) {
            kload(kh_, kl_, vh_, vl_, (head + (size_t)(kt + 2) * 64) * 64, st, tid);
            asm volatile("cp.async.commit_group;" ::: "memory");
        }
    }

    // ---- epilogue: normalize, write bf16 hi/lo [b,t,C] ----
    const float i0 = 1.0f / l0, i1 = 1.0f / l1;
    const int row = q0 + warp * 16 + (lane >> 2);
    const size_t ob = ((size_t)b * T_DIM + row) * C_DIM + h * 64 + (lane & 3) * 2;
#pragma unroll
    for (int dnt = 0; dnt < 8; dnt++) {
        float v0 = o[dnt][0] * i0, v1 = o[dnt][1] * i0;
        uint32_t hp = packbf(v0, v1);
        *(uint32_t*)(ah_ + ob + dnt * 8) = hp;
        *(uint32_t*)(al_ + ob + dnt * 8) = packres(hp, v0, v1);
        float u0 = o[dnt][2] * i1, u1 = o[dnt][3] * i1;
        uint32_t hq = packbf(u0, u1);
        *(uint32_t*)(ah_ + ob + 8 * C_DIM + dnt * 8) = hq;
        *(uint32_t*)(al_ + ob + 8 * C_DIM + dnt * 8) = packres(hq, u0, u1);
    }
}

// ---------------------------------------------------------------------------
// launch
// ---------------------------------------------------------------------------
extern "C" void kernel_launch(void* const* d_in, const int* in_sizes, int n_in,
                              void* d_out, int out_size)
{
    const float* x    = (const float*)d_in[0];
    const float* wqkv = (const float*)d_in[1];
    const float* wout = (const float*)d_in[2];
    float* out = (float*)d_out;

    float* qkv;
    __nv_bfloat16 *xh, *xl, *wqh, *wql, *woh, *wol, *ah, *al;
    __nv_bfloat16 *qh2, *ql2, *kh2, *kl2, *vh2, *vl2;
    cudaGetSymbolAddress((void**)&qkv, g_qkv);
    cudaGetSymbolAddress((void**)&xh, g_xh);
    cudaGetSymbolAddress((void**)&xl, g_xl);
    cudaGetSymbolAddress((void**)&wqh, g_wqh);
    cudaGetSymbolAddress((void**)&wql, g_wql);
    cudaGetSymbolAddress((void**)&woh, g_woh);
    cudaGetSymbolAddress((void**)&wol, g_wol);
    cudaGetSymbolAddress((void**)&ah, g_ah);
    cudaGetSymbolAddress((void**)&al, g_al);
    cudaGetSymbolAddress((void**)&qh2, g_qh2);
    cudaGetSymbolAddress((void**)&ql2, g_ql2);
    cudaGetSymbolAddress((void**)&kh2, g_kh2);
    cudaGetSymbolAddress((void**)&kl2, g_kl2);
    cudaGetSymbolAddress((void**)&vh2, g_vh2);
    cudaGetSymbolAddress((void**)&vl2, g_vl2);

    const int gemm_smem = GNSTAGE * GSTAGE;     // 98304
    cudaFuncSetAttribute(gemm_bf16x3, cudaFuncAttributeMaxDynamicSharedMemorySize,
                         gemm_smem);
    const int attn_smem = ASOFF + 2 * AST;      // 98304
    cudaFuncSetAttribute(attn_mma, cudaFuncAttributeMaxDynamicSharedMemorySize,
                         attn_smem);

    // split inputs to bf16 hi/lo
    {
        int n4 = MROWS * KDIM / 4;
        split_bf16<<<(n4 + 255) / 256, 256>>>((const float4*)x,
            (uint32_t*)xh, (uint32_t*)xl, n4);
        n4 = 3 * C_DIM * KDIM / 4;
        split_bf16<<<(n4 + 255) / 256, 256>>>((const float4*)wqkv,
            (uint32_t*)wqh, (uint32_t*)wql, n4);
        n4 = C_DIM * KDIM / 4;
        split_bf16<<<(n4 + 255) / 256, 256>>>((const float4*)wout,
            (uint32_t*)woh, (uint32_t*)wol, n4);
    }

    // 1) QKV projection: [8192, 3072] fp32
    gemm_bf16x3<<<dim3(3 * C_DIM / 128, MROWS / 128), 256, gemm_smem>>>(
        xh, xl, wqh, wql, qkv, 3 * C_DIM, KDIM);

    // 1b) split qkv into per-head bf16 hi/lo [b,h,t,d]
    split_qkv<<<MROWS, 256>>>(qkv, qh2, ql2, kh2, kl2, vh2, vl2);

    // 2) flash attention (tensor-core), writes bf16 hi/lo att
    attn_mma<<<dim3(T_DIM / 128, H_DIM, B_DIM), 256, attn_smem>>>(
        qh2, ql2, kh2, kl2, vh2, vl2, ah, al);

    // 3) output projection: [8192, 1024]
    gemm_bf16x3<<<dim3(C_DIM / 128, MROWS / 128), 256, gemm_smem>>>(
        ah, al, woh, wol, out, C_DIM, KDIM);
}

// round 6
// speedup vs baseline: 2.8081x; 1.0021x over previous
#include <cuda_runtime.h>
#include <cuda_bf16.h>
#include <cstdint>

#define B_DIM 2
#define T_DIM 4096
#define C_DIM 1024
#define H_DIM 16
#define D_DIM 64
#define MROWS (B_DIM * T_DIM)   // 8192
#define KDIM  C_DIM             // 1024

// ---------------- static device scratch (no allocs allowed) ----------------
__device__ __align__(256) __nv_bfloat16 g_xh[(size_t)MROWS * KDIM];
__device__ __align__(256) __nv_bfloat16 g_xl[(size_t)MROWS * KDIM];
__device__ __align__(256) __nv_bfloat16 g_wqh[(size_t)3 * C_DIM * KDIM];
__device__ __align__(256) __nv_bfloat16 g_wql[(size_t)3 * C_DIM * KDIM];
__device__ __align__(256) __nv_bfloat16 g_woh[(size_t)C_DIM * KDIM];
__device__ __align__(256) __nv_bfloat16 g_wol[(size_t)C_DIM * KDIM];
__device__ __align__(256) __nv_bfloat16 g_ah[(size_t)MROWS * KDIM];
__device__ __align__(256) __nv_bfloat16 g_al[(size_t)MROWS * KDIM];

// per-head [b,h,t,d] bf16 hi/lo for attention
__device__ __align__(256) __nv_bfloat16 g_qh2[(size_t)MROWS * C_DIM];
__device__ __align__(256) __nv_bfloat16 g_ql2[(size_t)MROWS * C_DIM];
__device__ __align__(256) __nv_bfloat16 g_kh2[(size_t)MROWS * C_DIM];
__device__ __align__(256) __nv_bfloat16 g_kl2[(size_t)MROWS * C_DIM];
__device__ __align__(256) __nv_bfloat16 g_vh2[(size_t)MROWS * C_DIM];
__device__ __align__(256) __nv_bfloat16 g_vl2[(size_t)MROWS * C_DIM];

// ---------------------------------------------------------------------------
// PTX helpers
// ---------------------------------------------------------------------------
__device__ __forceinline__ uint32_t cvta_s(const void* p) {
    uint32_t a;
    asm("{ .reg .u64 t; cvta.to.shared.u64 t, %1; cvt.u32.u64 %0, t; }"
        : "=r"(a) : "l"(p));
    return a;
}

__device__ __forceinline__ void cp16(uint32_t dst, const void* src) {
    asm volatile("cp.async.cg.shared.global [%0], [%1], 16;"
                 :: "r"(dst), "l"(src) : "memory");
}

__device__ __forceinline__ void ldm4(uint32_t addr, uint32_t& r0, uint32_t& r1,
                                     uint32_t& r2, uint32_t& r3) {
    asm volatile("ldmatrix.sync.aligned.m8n8.x4.shared.b16 {%0,%1,%2,%3}, [%4];"
                 : "=r"(r0), "=r"(r1), "=r"(r2), "=r"(r3) : "r"(addr));
}

__device__ __forceinline__ void ldm4t(uint32_t addr, uint32_t& r0, uint32_t& r1,
                                      uint32_t& r2, uint32_t& r3) {
    asm volatile("ldmatrix.sync.aligned.m8n8.x4.trans.shared.b16 {%0,%1,%2,%3}, [%4];"
                 : "=r"(r0), "=r"(r1), "=r"(r2), "=r"(r3) : "r"(addr));
}

__device__ __forceinline__ void mma_bf16(float* d, const uint32_t* a,
                                         uint32_t b0, uint32_t b1) {
    asm volatile(
        "mma.sync.aligned.m16n8k16.row.col.f32.bf16.bf16.f32 "
        "{%0,%1,%2,%3}, {%4,%5,%6,%7}, {%8,%9}, {%0,%1,%2,%3};"
        : "+f"(d[0]), "+f"(d[1]), "+f"(d[2]), "+f"(d[3])
        : "r"(a[0]), "r"(a[1]), "r"(a[2]), "r"(a[3]), "r"(b0), "r"(b1));
}

__device__ __forceinline__ float ex2f(float x) {
    float y;
    asm("ex2.approx.f32 %0, %1;" : "=f"(y) : "f"(x));
    return y;
}

__device__ __forceinline__ uint32_t packbf(float lo, float hi) {
    uint32_t r;
    asm("cvt.rn.bf16x2.f32 %0, %1, %2;" : "=r"(r) : "f"(hi), "f"(lo));
    return r;
}
__device__ __forceinline__ uint32_t packres(uint32_t hp, float f0, float f1) {
    float h0 = __uint_as_float(hp << 16);
    float h1 = __uint_as_float(hp & 0xffff0000u);
    return packbf(f0 - h0, f1 - h1);
}

// SW128: row r (128B rows), 16B chunk c(0..7) -> byte offset
__device__ __forceinline__ uint32_t swz(uint32_t r, uint32_t c) {
    return r * 128 + ((c ^ (r & 7)) << 4);
}

// ---------------------------------------------------------------------------
// split fp32 -> bf16 hi + lo
// ---------------------------------------------------------------------------
__global__ __launch_bounds__(256) void split_bf16(
    const float4* __restrict__ in, uint32_t* __restrict__ hi,
    uint32_t* __restrict__ lo, int n4)
{
    int i = blockIdx.x * blockDim.x + threadIdx.x;
    if (i >= n4) return;
    float4 v = in[i];
    uint32_t h0 = packbf(v.x, v.y), h1 = packbf(v.z, v.w);
    hi[2 * i] = h0; hi[2 * i + 1] = h1;
    lo[2 * i] = packres(h0, v.x, v.y);
    lo[2 * i + 1] = packres(h1, v.z, v.w);
}

// ---------------------------------------------------------------------------
// 3-term split-bf16 GEMM, SW128 smem, single-barrier 3-stage pipeline.
// MODE 0: write fp32 C.   MODE 1: write bf16 hi/lo q/k/v in [b,h,t,d].
// ---------------------------------------------------------------------------
#define GTILE   16384
#define GSTAGE  32768
#define GNSTAGE 3

__device__ __forceinline__ void g_ldtile(
    const __nv_bfloat16* __restrict__ Gh, const __nv_bfloat16* __restrict__ Gl,
    int K, int row0, int k0, uint32_t base, int tid)
{
#pragma unroll
    for (int t = 0; t < 4; t++) {
        int idx = tid + t * 256;
        int r = idx >> 3, c = idx & 7;
        const __nv_bfloat16* src = (c < 4)
            ? Gh + (size_t)(row0 + r) * K + k0 + c * 8
            : Gl + (size_t)(row0 + r) * K + k0 + (c - 4) * 8;
        cp16(base + swz(r, c), src);
    }
}

template <int MODE>
__global__ __launch_bounds__(256, 2) void gemm_bf16x3(
    const __nv_bfloat16* __restrict__ Ah, const __nv_bfloat16* __restrict__ Al,
    const __nv_bfloat16* __restrict__ Bh, const __nv_bfloat16* __restrict__ Bl,
    float* __restrict__ C,
    __nv_bfloat16* __restrict__ qh, __nv_bfloat16* __restrict__ ql,
    __nv_bfloat16* __restrict__ kh, __nv_bfloat16* __restrict__ kl,
    __nv_bfloat16* __restrict__ vh, __nv_bfloat16* __restrict__ vl,
    int N, int K)
{
    extern __shared__ __align__(128) char smraw[];
    const uint32_t smbase = cvta_s(smraw);

    const int tid  = threadIdx.x;
    const int wid  = tid >> 5;
    const int lane = tid & 31;
    const int n0 = blockIdx.x * 128;
    const int m0 = blockIdx.y * 128;
    const int wm = (wid & 1) * 64;
    const int wn = (wid >> 1) * 32;
    const int lr = lane & 15;
    const int lc = lane >> 4;

    float acc[4][4][4];
#pragma unroll
    for (int i = 0; i < 4; i++)
#pragma unroll
        for (int j = 0; j < 4; j++)
#pragma unroll
            for (int k = 0; k < 4; k++) acc[i][j][k] = 0.0f;

    const int nch = K / 32;

    // prologue: stages 0 and 1
#pragma unroll
    for (int c = 0; c < 2; c++) {
        uint32_t sb = smbase + c * GSTAGE;
        g_ldtile(Ah, Al, K, m0, c * 32, sb, tid);
        g_ldtile(Bh, Bl, K, n0, c * 32, sb + GTILE, tid);
        asm volatile("cp.async.commit_group;" ::: "memory");
    }

    for (int c = 0; c < nch; c++) {
        if (c + 1 < nch)
            asm volatile("cp.async.wait_group 1;" ::: "memory");
        else
            asm volatile("cp.async.wait_group 0;" ::: "memory");
        __syncthreads();

        // stage c+2 into buffer (c+2)%3 == (c-1)%3 (reads finished pre-barrier)
        if (c + 2 < nch) {
            uint32_t db = smbase + ((c + 2) % GNSTAGE) * GSTAGE;
            int kk = (c + 2) * 32;
            g_ldtile(Ah, Al, K, m0, kk, db, tid);
            g_ldtile(Bh, Bl, K, n0, kk, db + GTILE, tid);
            asm volatile("cp.async.commit_group;" ::: "memory");
        }

        uint32_t sb = smbase + (c % GNSTAGE) * GSTAGE;

#pragma unroll
        for (int ks = 0; ks < 2; ks++) {
            const uint32_t ch = ks * 2 + lc;
            uint32_t ah[4][4], al4[4][4];
#pragma unroll
            for (int mt = 0; mt < 4; mt++) {
                uint32_t row = wm + mt * 16 + lr;
                uint32_t rb = sb + row * 128;
                uint32_t key = row & 7;
                ldm4(rb + ((ch ^ key) << 4),
                     ah[mt][0], ah[mt][1], ah[mt][2], ah[mt][3]);
                ldm4(rb + (((ch + 4) ^ key) << 4),
                     al4[mt][0], al4[mt][1], al4[mt][2], al4[mt][3]);
            }
            uint32_t bh[2][4], bl[2][4];
#pragma unroll
            for (int p = 0; p < 2; p++) {
                uint32_t row = wn + p * 16 + lr;
                uint32_t rb = sb + GTILE + row * 128;
                uint32_t key = row & 7;
                ldm4(rb + ((ch ^ key) << 4),
                     bh[p][0], bh[p][1], bh[p][2], bh[p][3]);
                ldm4(rb + (((ch + 4) ^ key) << 4),
                     bl[p][0], bl[p][1], bl[p][2], bl[p][3]);
            }
#pragma unroll
            for (int mt = 0; mt < 4; mt++) {
#pragma unroll
                for (int nt = 0; nt < 4; nt++) {
                    const int p = nt >> 1, h = nt & 1;
                    mma_bf16(acc[mt][nt], ah[mt],  bh[p][h], bh[p][2 + h]);
                    mma_bf16(acc[mt][nt], al4[mt], bh[p][h], bh[p][2 + h]);
                    mma_bf16(acc[mt][nt], ah[mt],  bl[p][h], bl[p][2 + h]);
                }
            }
        }
    }

    const int er = lane >> 2;
    const int ec = (lane & 3) * 2;
#pragma unroll
    for (int mt = 0; mt < 4; mt++) {
#pragma unroll
        for (int nt = 0; nt < 4; nt++) {
            if (MODE == 0) {
                size_t row = (size_t)(m0 + wm + mt * 16 + er);
                int col = n0 + wn + nt * 8 + ec;
                *(float2*)(C + row * N + col) =
                    make_float2(acc[mt][nt][0], acc[mt][nt][1]);
                *(float2*)(C + (row + 8) * N + col) =
                    make_float2(acc[mt][nt][2], acc[mt][nt][3]);
            } else {
                int col = n0 + wn + nt * 8 + ec;       // 0..3071
                int type = col >> 10;
                int hh = (col >> 6) & 15;
                int d = col & 63;
                __nv_bfloat16* dh = (type == 0) ? qh : (type == 1) ? kh : vh;
                __nv_bfloat16* dl = (type == 0) ? ql : (type == 1) ? kl : vl;
#pragma unroll
                for (int rr = 0; rr < 2; rr++) {
                    int row = m0 + wm + mt * 16 + er + rr * 8;
                    int bb = row >> 12, tt = row & 4095;
                    size_t o = ((size_t)(bb * H_DIM + hh) * T_DIM + tt) * 64 + d;
                    float v0 = acc[mt][nt][2 * rr], v1 = acc[mt][nt][2 * rr + 1];
                    uint32_t hp = packbf(v0, v1);
                    *(uint32_t*)(dh + o) = hp;
                    *(uint32_t*)(dl + o) = packres(hp, v0, v1);
                }
            }
        }
    }
}

// ---------------------------------------------------------------------------
// Flash attention on mma.sync, split-bf16, causal.
// Br=128 (8 warps), Bc=64, SW128 smem, 2-stage, single barrier per iter.
// ---------------------------------------------------------------------------
#define AQT 16384
#define AKT 8192
#define AST 32768
#define ASOFF 32768

__device__ __forceinline__ void kload(
    const __nv_bfloat16* __restrict__ kh, const __nv_bfloat16* __restrict__ kl,
    const __nv_bfloat16* __restrict__ vh, const __nv_bfloat16* __restrict__ vl,
    size_t gbase, uint32_t st, int tid)
{
    const __nv_bfloat16* ptrs[4] = {kh, kl, vh, vl};
#pragma unroll
    for (int t = 0; t < 8; t++) {
        int idx = tid + t * 256;
        int tile = idx >> 9;
        int rem = idx & 511;
        int r = rem >> 3, c = rem & 7;
        cp16(st + tile * AKT + swz(r, c),
             ptrs[tile] + gbase + (size_t)r * 64 + c * 8);
    }
}

__global__ __launch_bounds__(256, 2) void attn_mma(
    const __nv_bfloat16* __restrict__ qh_, const __nv_bfloat16* __restrict__ ql_,
    const __nv_bfloat16* __restrict__ kh_, const __nv_bfloat16* __restrict__ kl_,
    const __nv_bfloat16* __restrict__ vh_, const __nv_bfloat16* __restrict__ vl_,
    __nv_bfloat16* __restrict__ ah_, __nv_bfloat16* __restrict__ al_)
{
    extern __shared__ __align__(128) char smraw2[];
    const uint32_t sb = cvta_s(smraw2);
    const int qt = gridDim.x - 1 - blockIdx.x;   // heavy tiles first
    const int h = blockIdx.y, b = blockIdx.z;
    const int tid = threadIdx.x, warp = tid >> 5, lane = tid & 31;
    const int q0 = qt * 128;
    const size_t head = (size_t)(b * H_DIM + h) * T_DIM;
    const int nkt = 2 * qt + 2;
    const int lr = lane & 15, lc = lane >> 4;

    // ---- prologue: Q (hi/lo) + stage0 ----
    {
        size_t g = (head + q0) * 64;
#pragma unroll
        for (int t = 0; t < 8; t++) {
            int idx = tid + t * 256;
            int tile = idx >> 10;
            int rem = idx & 1023;
            int r = rem >> 3, c = rem & 7;
            cp16(sb + tile * AQT + swz(r, c),
                 (tile ? ql_ : qh_) + g + (size_t)r * 64 + c * 8);
        }
        kload(kh_, kl_, vh_, vl_, head * 64, sb + ASOFF, tid);
        asm volatile("cp.async.commit_group;" ::: "memory");
        asm volatile("cp.async.wait_group 0;" ::: "memory");
    }
    __syncthreads();

    // ---- Q fragments ----
    uint32_t qf[4][4], qg[4][4];
    {
        uint32_t row = warp * 16 + lr;
        uint32_t rb = sb + row * 128;
        uint32_t key = row & 7;
#pragma unroll
        for (int ks = 0; ks < 4; ks++) {
            uint32_t ch = ks * 2 + lc;
            ldm4(rb + ((ch ^ key) << 4),
                 qf[ks][0], qf[ks][1], qf[ks][2], qf[ks][3]);
            ldm4(rb + AQT + ((ch ^ key) << 4),
                 qg[ks][0], qg[ks][1], qg[ks][2], qg[ks][3]);
        }
    }

    float m0 = -1e30f, m1 = -1e30f, l0 = 0.0f, l1 = 0.0f;
    float o[8][4];
#pragma unroll
    for (int i = 0; i < 8; i++)
#pragma unroll
        for (int j = 0; j < 4; j++) o[i][j] = 0.0f;

    const float SC = 0.180336880f;   // 0.125 * log2(e)
    const int grow = q0 + warp * 16;

    for (int kt = 0; kt < nkt; kt++) {
        if (kt > 0) {
            asm volatile("cp.async.wait_group 0;" ::: "memory");
            __syncthreads();
        }
        // issue next stage into the other buffer (reads of it done pre-barrier)
        if (kt + 1 < nkt) {
            kload(kh_, kl_, vh_, vl_, (head + (size_t)(kt + 1) * 64) * 64,
                  sb + ASOFF + ((kt + 1) & 1) * AST, tid);
            asm volatile("cp.async.commit_group;" ::: "memory");
        }
        const uint32_t st = sb + ASOFF + (kt & 1) * AST;

        // ---- S = Q K^T (3-term) ----
        float s[8][4];
#pragma unroll
        for (int i = 0; i < 8; i++)
#pragma unroll
            for (int j = 0; j < 4; j++) s[i][j] = 0.0f;

#pragma unroll
        for (int ks = 0; ks < 4; ks++) {
            uint32_t ch = ks * 2 + lc;
#pragma unroll
            for (int ng = 0; ng < 4; ng++) {
                uint32_t row = ng * 16 + lr;
                uint32_t rb = st + row * 128;
                uint32_t key = row & 7;
                uint32_t h0, h1, h2, h3, g0, g1, g2, g3;
                ldm4(rb + ((ch ^ key) << 4), h0, h1, h2, h3);
                ldm4(rb + AKT + ((ch ^ key) << 4), g0, g1, g2, g3);
                mma_bf16(s[2 * ng],     qf[ks], h0, h2);
                mma_bf16(s[2 * ng],     qg[ks], h0, h2);
                mma_bf16(s[2 * ng],     qf[ks], g0, g2);
                mma_bf16(s[2 * ng + 1], qf[ks], h1, h3);
                mma_bf16(s[2 * ng + 1], qg[ks], h1, h3);
                mma_bf16(s[2 * ng + 1], qf[ks], g1, g3);
            }
        }

        // ---- causal mask ----
        if (kt * 64 + 63 > grow) {
            const int rb0 = grow + (lane >> 2);
            const int cb = kt * 64 + (lane & 3) * 2;
#pragma unroll
            for (int nt = 0; nt < 8; nt++) {
                int c0 = cb + nt * 8;
                if (c0     > rb0)     s[nt][0] = -1e30f;
                if (c0 + 1 > rb0)     s[nt][1] = -1e30f;
                if (c0     > rb0 + 8) s[nt][2] = -1e30f;
                if (c0 + 1 > rb0 + 8) s[nt][3] = -1e30f;
            }
        }

        // ---- online softmax (base-2) ----
        float mx0 = s[0][0], mx1 = s[0][2];
#pragma unroll
        for (int nt = 0; nt < 8; nt++) {
            mx0 = fmaxf(mx0, fmaxf(s[nt][0], s[nt][1]));
            mx1 = fmaxf(mx1, fmaxf(s[nt][2], s[nt][3]));
        }
        mx0 = fmaxf(mx0, __shfl_xor_sync(0xffffffffu, mx0, 1));
        mx0 = fmaxf(mx0, __shfl_xor_sync(0xffffffffu, mx0, 2));
        mx1 = fmaxf(mx1, __shfl_xor_sync(0xffffffffu, mx1, 1));
        mx1 = fmaxf(mx1, __shfl_xor_sync(0xffffffffu, mx1, 2));

        float mn0 = fmaxf(m0, mx0), mn1 = fmaxf(m1, mx1);
        float a0 = ex2f((m0 - mn0) * SC), a1 = ex2f((m1 - mn1) * SC);
        m0 = mn0; m1 = mn1;

        float rs0 = 0.0f, rs1 = 0.0f;
#pragma unroll
        for (int nt = 0; nt < 8; nt++) {
            s[nt][0] = ex2f((s[nt][0] - mn0) * SC);
            s[nt][1] = ex2f((s[nt][1] - mn0) * SC);
            s[nt][2] = ex2f((s[nt][2] - mn1) * SC);
            s[nt][3] = ex2f((s[nt][3] - mn1) * SC);
            rs0 += s[nt][0] + s[nt][1];
            rs1 += s[nt][2] + s[nt][3];
        }
        rs0 += __shfl_xor_sync(0xffffffffu, rs0, 1);
        rs0 += __shfl_xor_sync(0xffffffffu, rs0, 2);
        rs1 += __shfl_xor_sync(0xffffffffu, rs1, 1);
        rs1 += __shfl_xor_sync(0xffffffffu, rs1, 2);
        l0 = l0 * a0 + rs0;
        l1 = l1 * a1 + rs1;

#pragma unroll
        for (int i = 0; i < 8; i++) {
            o[i][0] *= a0; o[i][1] *= a0;
            o[i][2] *= a1; o[i][3] *= a1;
        }

        // ---- O += P V (3-term) ----
#pragma unroll
        for (int ks2 = 0; ks2 < 4; ks2++) {
            uint32_t pa[4], pb[4];
            pa[0] = packbf(s[2 * ks2][0],     s[2 * ks2][1]);
            pa[1] = packbf(s[2 * ks2][2],     s[2 * ks2][3]);
            pa[2] = packbf(s[2 * ks2 + 1][0], s[2 * ks2 + 1][1]);
            pa[3] = packbf(s[2 * ks2 + 1][2], s[2 * ks2 + 1][3]);
            pb[0] = packres(pa[0], s[2 * ks2][0],     s[2 * ks2][1]);
            pb[1] = packres(pa[1], s[2 * ks2][2],     s[2 * ks2][3]);
            pb[2] = packres(pa[2], s[2 * ks2 + 1][0], s[2 * ks2 + 1][1]);
            pb[3] = packres(pa[3], s[2 * ks2 + 1][2], s[2 * ks2 + 1][3]);

            uint32_t row = ks2 * 16 + lr;
            uint32_t rb = st + 2 * AKT + row * 128;
            uint32_t key = row & 7;
#pragma unroll
            for (int dg = 0; dg < 4; dg++) {
                uint32_t ch = dg * 2 + lc;
                uint32_t a = rb + ((ch ^ key) << 4);
                uint32_t v0, v1, v2, v3, w0, w1, w2, w3;
                ldm4t(a, v0, v1, v2, v3);
                ldm4t(a + AKT, w0, w1, w2, w3);
                mma_bf16(o[2 * dg],     pa, v0, v1);
                mma_bf16(o[2 * dg],     pb, v0, v1);
                mma_bf16(o[2 * dg],     pa, w0, w1);
                mma_bf16(o[2 * dg + 1], pa, v2, v3);
                mma_bf16(o[2 * dg + 1], pb, v2, v3);
                mma_bf16(o[2 * dg + 1], pa, w2, w3);
            }
        }
    }

    // ---- epilogue: normalize, write bf16 hi/lo [b,t,C] ----
    const float i0 = 1.0f / l0, i1 = 1.0f / l1;
    const int row = q0 + warp * 16 + (lane >> 2);
    const size_t ob = ((size_t)b * T_DIM + row) * C_DIM + h * 64 + (lane & 3) * 2;
#pragma unroll
    for (int dnt = 0; dnt < 8; dnt++) {
        float v0 = o[dnt][0] * i0, v1 = o[dnt][1] * i0;
        uint32_t hp = packbf(v0, v1);
        *(uint32_t*)(ah_ + ob + dnt * 8) = hp;
        *(uint32_t*)(al_ + ob + dnt * 8) = packres(hp, v0, v1);
        float u0 = o[dnt][2] * i1, u1 = o[dnt][3] * i1;
        uint32_t hq = packbf(u0, u1);
        *(uint32_t*)(ah_ + ob + 8 * C_DIM + dnt * 8) = hq;
        *(uint32_t*)(al_ + ob + 8 * C_DIM + dnt * 8) = packres(hq, u0, u1);
    }
}

// ---------------------------------------------------------------------------
// launch
// ---------------------------------------------------------------------------
extern "C" void kernel_launch(void* const* d_in, const int* in_sizes, int n_in,
                              void* d_out, int out_size)
{
    const float* x    = (const float*)d_in[0];
    const float* wqkv = (const float*)d_in[1];
    const float* wout = (const float*)d_in[2];
    float* out = (float*)d_out;

    __nv_bfloat16 *xh, *xl, *wqh, *wql, *woh, *wol, *ah, *al;
    __nv_bfloat16 *qh2, *ql2, *kh2, *kl2, *vh2, *vl2;
    cudaGetSymbolAddress((void**)&xh, g_xh);
    cudaGetSymbolAddress((void**)&xl, g_xl);
    cudaGetSymbolAddress((void**)&wqh, g_wqh);
    cudaGetSymbolAddress((void**)&wql, g_wql);
    cudaGetSymbolAddress((void**)&woh, g_woh);
    cudaGetSymbolAddress((void**)&wol, g_wol);
    cudaGetSymbolAddress((void**)&ah, g_ah);
    cudaGetSymbolAddress((void**)&al, g_al);
    cudaGetSymbolAddress((void**)&qh2, g_qh2);
    cudaGetSymbolAddress((void**)&ql2, g_ql2);
    cudaGetSymbolAddress((void**)&kh2, g_kh2);
    cudaGetSymbolAddress((void**)&kl2, g_kl2);
    cudaGetSymbolAddress((void**)&vh2, g_vh2);
    cudaGetSymbolAddress((void**)&vl2, g_vl2);

    const int gemm_smem = GNSTAGE * GSTAGE;     // 98304
    cudaFuncSetAttribute(gemm_bf16x3<0>, cudaFuncAttributeMaxDynamicSharedMemorySize,
                         gemm_smem);
    cudaFuncSetAttribute(gemm_bf16x3<1>, cudaFuncAttributeMaxDynamicSharedMemorySize,
                         gemm_smem);
    const int attn_smem = ASOFF + 2 * AST;      // 98304
    cudaFuncSetAttribute(attn_mma, cudaFuncAttributeMaxDynamicSharedMemorySize,
                         attn_smem);

    // split inputs to bf16 hi/lo
    {
        int n4 = MROWS * KDIM / 4;
        split_bf16<<<(n4 + 255) / 256, 256>>>((const float4*)x,
            (uint32_t*)xh, (uint32_t*)xl, n4);
        n4 = 3 * C_DIM * KDIM / 4;
        split_bf16<<<(n4 + 255) / 256, 256>>>((const float4*)wqkv,
            (uint32_t*)wqh, (uint32_t*)wql, n4);
        n4 = C_DIM * KDIM / 4;
        split_bf16<<<(n4 + 255) / 256, 256>>>((const float4*)wout,
            (uint32_t*)woh, (uint32_t*)wol, n4);
    }

    // 1) QKV projection, fused split epilogue -> q/k/v hi/lo [b,h,t,d]
    gemm_bf16x3<1><<<dim3(3 * C_DIM / 128, MROWS / 128), 256, gemm_smem>>>(
        xh, xl, wqh, wql, nullptr,
        qh2, ql2, kh2, kl2, vh2, vl2, 3 * C_DIM, KDIM);

    // 2) flash attention (tensor-core), writes bf16 hi/lo att
    attn_mma<<<dim3(T_DIM / 128, H_DIM, B_DIM), 256, attn_smem>>>(
        qh2, ql2, kh2, kl2, vh2, vl2, ah, al);

    // 3) output projection: [8192, 1024] fp32
    gemm_bf16x3<0><<<dim3(C_DIM / 128, MROWS / 128), 256, gemm_smem>>>(
        ah, al, woh, wol, out,
        nullptr, nullptr, nullptr, nullptr, nullptr, nullptr, C_DIM, KDIM);
}